// round 4
// baseline (speedup 1.0000x reference)
#include <cuda_runtime.h>
#include <math.h>

// ---------------- problem constants ----------------
#define BB      8
#define NN_     1024
#define DIM_    512
#define HH      8
#define DD      64
#define INNER_  512
#define MTOK    3
#define CTX     2048            // 2*N
#define LK      2051            // 2N + M
#define LS      1027            // N + M
#define SCALE_  0.125f          // 64^-0.5
#define SQRT_D  8.0f
#define SQRT_M  1.7320508075688772f

// ---------------- scratch (device globals; no allocation allowed) ----------------
__device__ float g_ctx  [CTX * BB * DIM_];          // 32 MB
__device__ float g_kctx [CTX * BB * INNER_];        // 32 MB
__device__ float g_skv  [BB * NN_ * 2 * INNER_];    // 32 MB
__device__ float g_qlin [BB * NN_ * INNER_];        // 16 MB
__device__ float g_Q    [BB * HH * NN_ * DD];       // 16 MB
__device__ float g_K    [BB * HH * LK * DD];        // 67 MB
__device__ float g_Sk   [BB * HH * LS * DD];        // 34 MB
__device__ float g_SvT  [BB * HH * DD * LS];        // 34 MB
__device__ float g_P    [(size_t)BB * HH * NN_ * LK];  // 537 MB
__device__ float g_S2   [(size_t)BB * HH * NN_ * LS];  // 269 MB (attn written in-place)
__device__ float g_obh  [BB * HH * NN_ * DD];       // 16 MB
__device__ float g_out  [BB * NN_ * INNER_];        // 16 MB

// ---------------- generic NT SGEMM: C = alpha*(A @ W^T) + bias + add ----------------
// A: [M,K] row-major (lda), W: [N,K] row-major (ldw), C: [M,N] (ldc)
// batched via blockIdx.z with element strides sA/sW/sC/sAdd.
// NOTE: C == addm (in-place) is safe: each thread reads addm[r,c] once before
// writing C[r,c], and no other thread touches that element.
#define BM 64
#define BN 64
#define BK 16

__global__ __launch_bounds__(256)
void gemm_nt(const float* __restrict__ A, int lda, long sA,
             const float* __restrict__ W, int ldw, long sW,
             const float* __restrict__ bias,
             const float* __restrict__ addm, int ldadd, long sAdd,
             float* __restrict__ C, int ldc, long sC,
             int M, int N, int K, float alpha)
{
    __shared__ float As[BK][BM];
    __shared__ float Bs[BK][BN];

    const long bz = blockIdx.z;
    const float* Ab = A + bz * sA;
    const float* Wb = W + bz * sW;
    const float* Addb = addm ? (addm + bz * sAdd) : nullptr;
    float* Cb = C + bz * sC;

    const int row0 = blockIdx.y * BM;
    const int col0 = blockIdx.x * BN;
    const int tid = threadIdx.y * 16 + threadIdx.x;
    const int ty4 = threadIdx.y * 4;
    const int tx4 = threadIdx.x * 4;

    float acc[4][4] = {};

    for (int k0 = 0; k0 < K; k0 += BK) {
        #pragma unroll
        for (int i = 0; i < 4; i++) {
            int e = tid + i * 256;
            int r  = e >> 4;
            int kk = e & 15;
            int gk = k0 + kk;
            int gr = row0 + r;
            As[kk][r] = (gr < M && gk < K) ? Ab[(long)gr * lda + gk] : 0.0f;
            int gn = col0 + r;
            Bs[kk][r] = (gn < N && gk < K) ? Wb[(long)gn * ldw + gk] : 0.0f;
        }
        __syncthreads();

        #pragma unroll
        for (int kk = 0; kk < BK; kk++) {
            float4 ra = *reinterpret_cast<const float4*>(&As[kk][ty4]);
            float4 rb = *reinterpret_cast<const float4*>(&Bs[kk][tx4]);
            float a[4] = {ra.x, ra.y, ra.z, ra.w};
            float b[4] = {rb.x, rb.y, rb.z, rb.w};
            #pragma unroll
            for (int i = 0; i < 4; i++)
                #pragma unroll
                for (int j = 0; j < 4; j++)
                    acc[i][j] = fmaf(a[i], b[j], acc[i][j]);
        }
        __syncthreads();
    }

    #pragma unroll
    for (int i = 0; i < 4; i++) {
        int r = row0 + ty4 + i;
        if (r >= M) continue;
        #pragma unroll
        for (int j = 0; j < 4; j++) {
            int c = col0 + tx4 + j;
            if (c >= N) continue;
            float v = alpha * acc[i][j];
            if (bias) v += bias[c];
            if (Addb) v += Addb[(long)r * ldadd + c];
            Cb[(long)r * ldc + c] = v;
        }
    }
}

// ---------------- row softmax (one block per row) ----------------
__global__ __launch_bounds__(256)
void softmax_rows(float* __restrict__ data, int cols)
{
    const long row = blockIdx.x;
    float* p = data + row * (long)cols;
    const int tid = threadIdx.x;
    __shared__ float sh[256];

    float mx = -3.0e38f;
    for (int c = tid; c < cols; c += 256) mx = fmaxf(mx, p[c]);
    sh[tid] = mx; __syncthreads();
    for (int s = 128; s > 0; s >>= 1) {
        if (tid < s) sh[tid] = fmaxf(sh[tid], sh[tid + s]);
        __syncthreads();
    }
    mx = sh[0]; __syncthreads();

    float sum = 0.0f;
    for (int c = tid; c < cols; c += 256) {
        float e = __expf(p[c] - mx);
        p[c] = e;
        sum += e;
    }
    sh[tid] = sum; __syncthreads();
    for (int s = 128; s > 0; s >>= 1) {
        if (tid < s) sh[tid] += sh[tid + s];
        __syncthreads();
    }
    float inv = 1.0f / sh[0];
    for (int c = tid; c < cols; c += 256) p[c] *= inv;
}

// ---------------- pack kernels ----------------
__global__ void pack_ctx(const float* __restrict__ x, const float* __restrict__ y)
{
    long idx = (long)blockIdx.x * blockDim.x + threadIdx.x;
    const long total = (long)CTX * BB * DIM_;
    if (idx >= total) return;
    long b = idx / ((long)CTX * DIM_);
    long rem = idx - b * (long)CTX * DIM_;
    long j = rem / DIM_;
    long c = rem - j * DIM_;
    g_ctx[idx] = (j < NN_) ? x[(b * NN_ + j) * DIM_ + c]
                           : y[(b * NN_ + (j - NN_)) * DIM_ + c];
}

__global__ void pack_Q()
{
    long idx = (long)blockIdx.x * blockDim.x + threadIdx.x;
    const long total = (long)BB * HH * NN_ * DD;
    if (idx >= total) return;
    long z = idx / ((long)NN_ * DD);
    long rem = idx - z * (long)NN_ * DD;
    long n = rem / DD, d = rem - n * DD;
    long b = z >> 3, h = z & 7;
    g_Q[idx] = g_qlin[(b * NN_ + n) * INNER_ + h * DD + d];
}

__global__ void pack_K(const float* __restrict__ m_k)
{
    long idx = (long)blockIdx.x * blockDim.x + threadIdx.x;
    const long total = (long)BB * HH * LK * DD;
    if (idx >= total) return;
    long z = idx / ((long)LK * DD);
    long rem = idx - z * (long)LK * DD;
    long j = rem / DD, d = rem - j * DD;
    long b = z >> 3, h = z & 7;
    g_K[idx] = (j < CTX) ? g_kctx[(b * CTX + j) * INNER_ + h * DD + d]
                         : SQRT_D * m_k[h * (MTOK * DD) + (j - CTX) * DD + d];
}

__global__ void pack_Sk(const float* __restrict__ Sm_k)
{
    long idx = (long)blockIdx.x * blockDim.x + threadIdx.x;
    const long total = (long)BB * HH * LS * DD;
    if (idx >= total) return;
    long z = idx / ((long)LS * DD);
    long rem = idx - z * (long)LS * DD;
    long j = rem / DD, d = rem - j * DD;
    long b = z >> 3, h = z & 7;
    g_Sk[idx] = (j < NN_) ? g_skv[(b * NN_ + j) * (2 * INNER_) + h * DD + d]
                          : SQRT_D * Sm_k[h * (MTOK * DD) + (j - NN_) * DD + d];
}

__global__ void pack_SvT(const float* __restrict__ Sm_v)
{
    long idx = (long)blockIdx.x * blockDim.x + threadIdx.x;
    const long total = (long)BB * HH * DD * LS;
    if (idx >= total) return;
    long z = idx / ((long)DD * LS);
    long rem = idx - z * (long)DD * LS;
    long d = rem / LS, j = rem - d * LS;
    long b = z >> 3, h = z & 7;
    g_SvT[idx] = (j < NN_) ? g_skv[(b * NN_ + j) * (2 * INNER_) + INNER_ + h * DD + d]
                           : SQRT_M * Sm_v[h * (MTOK * DD) + (j - NN_) * DD + d];
}

__global__ void pack_out()
{
    long idx = (long)blockIdx.x * blockDim.x + threadIdx.x;
    const long total = (long)BB * NN_ * INNER_;
    if (idx >= total) return;
    long b = idx / ((long)NN_ * INNER_);
    long rem = idx - b * (long)NN_ * INNER_;
    long n = rem / INNER_;
    long c = rem - n * INNER_;
    long h = c / DD, d = c - h * DD;
    g_out[idx] = g_obh[((b * HH + h) * NN_ + n) * DD + d];
}

// ---------------- launch ----------------
static inline dim3 eltGrid(long n) { return dim3((unsigned)((n + 255) / 256)); }

extern "C" void kernel_launch(void* const* d_in, const int* in_sizes, int n_in,
                              void* d_out, int out_size)
{
    const float* inp  = (const float*)d_in[0];
    const float* x    = (const float*)d_in[1];
    const float* y    = (const float*)d_in[2];
    const float* Wq   = (const float*)d_in[3];
    const float* bq   = (const float*)d_in[4];
    const float* Wkv  = (const float*)d_in[5];
    const float* bkv  = (const float*)d_in[6];
    const float* Wf   = (const float*)d_in[7];
    const float* bf   = (const float*)d_in[8];
    const float* Wo   = (const float*)d_in[9];
    const float* bo   = (const float*)d_in[10];
    const float* m_k  = (const float*)d_in[11];
    // d_in[12] = m_v : unused (cross-attention v never feeds the output)
    const float* Sm_k = (const float*)d_in[13];
    const float* Sm_v = (const float*)d_in[14];
    float* out = (float*)d_out;

    float* p_ctx;  cudaGetSymbolAddress((void**)&p_ctx,  g_ctx);
    float* p_kctx; cudaGetSymbolAddress((void**)&p_kctx, g_kctx);
    float* p_skv;  cudaGetSymbolAddress((void**)&p_skv,  g_skv);
    float* p_qlin; cudaGetSymbolAddress((void**)&p_qlin, g_qlin);
    float* p_Q;    cudaGetSymbolAddress((void**)&p_Q,    g_Q);
    float* p_K;    cudaGetSymbolAddress((void**)&p_K,    g_K);
    float* p_Sk;   cudaGetSymbolAddress((void**)&p_Sk,   g_Sk);
    float* p_SvT;  cudaGetSymbolAddress((void**)&p_SvT,  g_SvT);
    float* p_P;    cudaGetSymbolAddress((void**)&p_P,    g_P);
    float* p_S2;   cudaGetSymbolAddress((void**)&p_S2,   g_S2);
    float* p_obh;  cudaGetSymbolAddress((void**)&p_obh,  g_obh);
    float* p_out;  cudaGetSymbolAddress((void**)&p_out,  g_out);

    dim3 thr(16, 16);

    // 1. context = concat(x, y)
    pack_ctx<<<eltGrid((long)CTX * BB * DIM_), 256>>>(x, y);

    // 2. q_lin = inp @ Wq^T + bq   [8192, 512]
    gemm_nt<<<dim3(512 / BN, (BB * NN_) / BM, 1), thr>>>(
        inp, DIM_, 0, Wq, DIM_, 0, bq, nullptr, 0, 0,
        p_qlin, INNER_, 0, BB * NN_, INNER_, DIM_, 1.0f);

    // 3. k_ctx = context @ Wkv[0:512]^T + bkv[0:512]   [16384, 512]  (v half is dead)
    gemm_nt<<<dim3(512 / BN, (BB * CTX) / BM, 1), thr>>>(
        p_ctx, DIM_, 0, Wkv, DIM_, 0, bkv, nullptr, 0, 0,
        p_kctx, INNER_, 0, BB * CTX, INNER_, DIM_, 1.0f);

    // 4. skv = inp @ Wkv^T + bkv   [8192, 1024]
    gemm_nt<<<dim3(1024 / BN, (BB * NN_) / BM, 1), thr>>>(
        inp, DIM_, 0, Wkv, DIM_, 0, bkv, nullptr, 0, 0,
        p_skv, 2 * INNER_, 0, BB * NN_, 2 * INNER_, DIM_, 1.0f);

    // 5. head-split packs (+ memory tokens)
    pack_Q  <<<eltGrid((long)BB * HH * NN_ * DD), 256>>>();
    pack_K  <<<eltGrid((long)BB * HH * LK * DD), 256>>>(m_k);
    pack_Sk <<<eltGrid((long)BB * HH * LS * DD), 256>>>(Sm_k);
    pack_SvT<<<eltGrid((long)BB * HH * DD * LS), 256>>>(Sm_v);

    // 6. cross scores: P[z] = SCALE * Q[z] @ K[z]^T    [64 x 1024 x 2051]
    gemm_nt<<<dim3((LK + BN - 1) / BN, NN_ / BM, BB * HH), thr>>>(
        p_Q, DD, (long)NN_ * DD, p_K, DD, (long)LK * DD, nullptr, nullptr, 0, 0,
        p_P, LK, (long)NN_ * LK, NN_, LK, DD, SCALE_);

    //    self scores: S2[z] = SCALE * Q[z] @ Sk[z]^T   [64 x 1024 x 1027]
    gemm_nt<<<dim3((LS + BN - 1) / BN, NN_ / BM, BB * HH), thr>>>(
        p_Q, DD, (long)NN_ * DD, p_Sk, DD, (long)LS * DD, nullptr, nullptr, 0, 0,
        p_S2, LS, (long)NN_ * LS, NN_, LS, DD, SCALE_);

    // 7. softmax
    softmax_rows<<<BB * HH * NN_, 256>>>(p_P, LK);
    softmax_rows<<<BB * HH * NN_, 256>>>(p_S2, LS);

    // 8. attn = P @ Wf^T + bf + S2, written IN-PLACE into S2
    //    (flat M=65536, N=1027, K=2051) — dominant GEMM, 276 GFLOP
    gemm_nt<<<dim3((LS + BN - 1) / BN, (BB * HH * NN_) / BM, 1), thr>>>(
        p_P, LK, 0, Wf, LK, 0, bf, p_S2, LS, 0,
        p_S2, LS, 0, BB * HH * NN_, LS, LK, 1.0f);

    // 9. obh[z] = attn[z] @ SvT[z]^T   [64 x 1024 x 64]
    gemm_nt<<<dim3(DD / BN, NN_ / BM, BB * HH), thr>>>(
        p_S2, LS, (long)NN_ * LS, p_SvT, LS, (long)DD * LS, nullptr, nullptr, 0, 0,
        p_obh, DD, (long)NN_ * DD, NN_, DD, LS, 1.0f);

    // 10. merge heads
    pack_out<<<eltGrid((long)BB * NN_ * INNER_), 256>>>();

    // 11. final = out @ Wo^T + bo   [8192, 512]
    gemm_nt<<<dim3(DIM_ / BN, (BB * NN_) / BM, 1), thr>>>(
        p_out, INNER_, 0, Wo, INNER_, 0, bo, nullptr, 0, 0,
        out, DIM_, 0, BB * NN_, DIM_, INNER_, 1.0f);
}

// round 5
// speedup vs baseline: 3.2300x; 3.2300x over previous
#include <cuda_runtime.h>
#include <math.h>

// ---------------- problem constants ----------------
#define BB      8
#define NN_     1024
#define DIM_    512
#define HH      8
#define DD      64
#define INNER_  512
#define MTOK    3
#define CTX     2048            // 2*N
#define LK      2051            // 2N + M
#define LS      1027            // N + M
#define SCALE_  0.125f          // 64^-0.5
#define SQRT_D  8.0f
#define SQRT_M  1.7320508075688772f

// ---------------- scratch (device globals; no allocation allowed) ----------------
__device__ float g_ctx  [CTX * BB * DIM_];          // 32 MB
__device__ float g_kctx [CTX * BB * INNER_];        // 32 MB
__device__ float g_skv  [BB * NN_ * 2 * INNER_];    // 32 MB
__device__ float g_qlin [BB * NN_ * INNER_];        // 16 MB
__device__ float g_Q    [BB * HH * NN_ * DD];       // 16 MB
__device__ float g_K    [BB * HH * LK * DD];        // 67 MB
__device__ float g_Sk   [BB * HH * LS * DD];        // 34 MB
__device__ float g_SvT  [BB * HH * DD * LS];        // 34 MB
__device__ float g_P    [(size_t)BB * HH * NN_ * LK];  // 537 MB
__device__ float g_S2   [(size_t)BB * HH * NN_ * LS];  // 269 MB (attn written in-place)
__device__ float g_obh  [BB * HH * NN_ * DD];       // 16 MB
__device__ float g_out  [BB * NN_ * INNER_];        // 16 MB

// ---------------- fast NT SGEMM: C = alpha*(A @ W^T) + bias + add ----------------
// A: [M,K] row-major (lda), W: [N,K] row-major (ldw), C: [M,N] (ldc)
// batched via blockIdx.z with strides sA/sW/sC/sAdd.
// 128x128x8 tile, 256 threads, 8x8 micro-tile, double-buffered smem.
// In-place C == addm is safe (each element read once by its own writer thread).
#define BM 128
#define BN 128
#define BK 8

__global__ __launch_bounds__(256, 2)
void gemm_nt(const float* __restrict__ A, int lda, long sA,
             const float* __restrict__ W, int ldw, long sW,
             const float* __restrict__ bias,
             const float* __restrict__ addm, int ldadd, long sAdd,
             float* __restrict__ C, int ldc, long sC,
             int M, int N, int K, float alpha)
{
    __shared__ float As[2][BK][BM];
    __shared__ float Bs[2][BK][BN];

    const long bz = blockIdx.z;
    const float* Ab   = A + bz * sA;
    const float* Wb   = W + bz * sW;
    const float* Addb = addm ? (addm + bz * sAdd) : nullptr;
    float* Cb = C + bz * sC;

    const int row0 = blockIdx.y * BM;
    const int col0 = blockIdx.x * BN;
    const int tid  = threadIdx.x;
    const int tx   = tid & 15;       // 0..15 -> output cols
    const int ty   = tid >> 4;       // 0..15 -> output rows

    // global->smem load mapping: each thread loads 4 consecutive k for one row
    const int ldRow = tid >> 1;          // 0..127
    const int ldK   = (tid & 1) * 4;     // 0 or 4
    const int gr = row0 + ldRow;         // A row
    const int gn = col0 + ldRow;         // W row (= C col)

    float acc[8][8] = {};
    float ra[4], rb[4];

    // ---- preload tile 0 ----
    #pragma unroll
    for (int i = 0; i < 4; i++) {
        int gk = ldK + i;
        ra[i] = (gr < M && gk < K) ? Ab[(long)gr * lda + gk] : 0.0f;
        rb[i] = (gn < N && gk < K) ? Wb[(long)gn * ldw + gk] : 0.0f;
    }
    #pragma unroll
    for (int i = 0; i < 4; i++) {
        As[0][ldK + i][ldRow] = ra[i];
        Bs[0][ldK + i][ldRow] = rb[i];
    }
    __syncthreads();

    int buf = 0;
    for (int k0 = 0; k0 < K; k0 += BK) {
        const int k1 = k0 + BK;
        // prefetch next tile into registers (overlaps with compute)
        if (k1 < K) {
            #pragma unroll
            for (int i = 0; i < 4; i++) {
                int gk = k1 + ldK + i;
                ra[i] = (gr < M && gk < K) ? Ab[(long)gr * lda + gk] : 0.0f;
                rb[i] = (gn < N && gk < K) ? Wb[(long)gn * ldw + gk] : 0.0f;
            }
        }

        // compute on current buffer
        #pragma unroll
        for (int kk = 0; kk < BK; kk++) {
            float4 a0 = *reinterpret_cast<const float4*>(&As[buf][kk][ty * 4]);
            float4 a1 = *reinterpret_cast<const float4*>(&As[buf][kk][ty * 4 + 64]);
            float4 b0 = *reinterpret_cast<const float4*>(&Bs[buf][kk][tx * 4]);
            float4 b1 = *reinterpret_cast<const float4*>(&Bs[buf][kk][tx * 4 + 64]);
            float a[8] = {a0.x, a0.y, a0.z, a0.w, a1.x, a1.y, a1.z, a1.w};
            float b[8] = {b0.x, b0.y, b0.z, b0.w, b1.x, b1.y, b1.z, b1.w};
            #pragma unroll
            for (int i = 0; i < 8; i++)
                #pragma unroll
                for (int j = 0; j < 8; j++)
                    acc[i][j] = fmaf(a[i], b[j], acc[i][j]);
        }

        if (k1 < K) {
            #pragma unroll
            for (int i = 0; i < 4; i++) {
                As[buf ^ 1][ldK + i][ldRow] = ra[i];
                Bs[buf ^ 1][ldK + i][ldRow] = rb[i];
            }
            __syncthreads();
            buf ^= 1;
        }
    }

    // ---- fused epilogue ----
    #pragma unroll
    for (int i = 0; i < 8; i++) {
        int r = row0 + ((i < 4) ? (ty * 4 + i) : (64 + ty * 4 + i - 4));
        if (r >= M) continue;
        #pragma unroll
        for (int j = 0; j < 8; j++) {
            int c = col0 + ((j < 4) ? (tx * 4 + j) : (64 + tx * 4 + j - 4));
            if (c >= N) continue;
            float v = alpha * acc[i][j];
            if (bias) v += bias[c];
            if (Addb) v += Addb[(long)r * ldadd + c];
            Cb[(long)r * ldc + c] = v;
        }
    }
}

// ---------------- row softmax (one block per row) ----------------
__global__ __launch_bounds__(256)
void softmax_rows(float* __restrict__ data, int cols)
{
    const long row = blockIdx.x;
    float* p = data + row * (long)cols;
    const int tid = threadIdx.x;
    __shared__ float sh[256];

    float mx = -3.0e38f;
    for (int c = tid; c < cols; c += 256) mx = fmaxf(mx, p[c]);
    sh[tid] = mx; __syncthreads();
    for (int s = 128; s > 0; s >>= 1) {
        if (tid < s) sh[tid] = fmaxf(sh[tid], sh[tid + s]);
        __syncthreads();
    }
    mx = sh[0]; __syncthreads();

    float sum = 0.0f;
    for (int c = tid; c < cols; c += 256) {
        float e = __expf(p[c] - mx);
        p[c] = e;
        sum += e;
    }
    sh[tid] = sum; __syncthreads();
    for (int s = 128; s > 0; s >>= 1) {
        if (tid < s) sh[tid] += sh[tid + s];
        __syncthreads();
    }
    float inv = 1.0f / sh[0];
    for (int c = tid; c < cols; c += 256) p[c] *= inv;
}

// ---------------- pack kernels ----------------
__global__ void pack_ctx(const float* __restrict__ x, const float* __restrict__ y)
{
    long idx = (long)blockIdx.x * blockDim.x + threadIdx.x;
    const long total = (long)CTX * BB * DIM_;
    if (idx >= total) return;
    long b = idx / ((long)CTX * DIM_);
    long rem = idx - b * (long)CTX * DIM_;
    long j = rem / DIM_;
    long c = rem - j * DIM_;
    g_ctx[idx] = (j < NN_) ? x[(b * NN_ + j) * DIM_ + c]
                           : y[(b * NN_ + (j - NN_)) * DIM_ + c];
}

__global__ void pack_Q()
{
    long idx = (long)blockIdx.x * blockDim.x + threadIdx.x;
    const long total = (long)BB * HH * NN_ * DD;
    if (idx >= total) return;
    long z = idx / ((long)NN_ * DD);
    long rem = idx - z * (long)NN_ * DD;
    long n = rem / DD, d = rem - n * DD;
    long b = z >> 3, h = z & 7;
    g_Q[idx] = g_qlin[(b * NN_ + n) * INNER_ + h * DD + d];
}

__global__ void pack_K(const float* __restrict__ m_k)
{
    long idx = (long)blockIdx.x * blockDim.x + threadIdx.x;
    const long total = (long)BB * HH * LK * DD;
    if (idx >= total) return;
    long z = idx / ((long)LK * DD);
    long rem = idx - z * (long)LK * DD;
    long j = rem / DD, d = rem - j * DD;
    long b = z >> 3, h = z & 7;
    g_K[idx] = (j < CTX) ? g_kctx[(b * CTX + j) * INNER_ + h * DD + d]
                         : SQRT_D * m_k[h * (MTOK * DD) + (j - CTX) * DD + d];
}

__global__ void pack_Sk(const float* __restrict__ Sm_k)
{
    long idx = (long)blockIdx.x * blockDim.x + threadIdx.x;
    const long total = (long)BB * HH * LS * DD;
    if (idx >= total) return;
    long z = idx / ((long)LS * DD);
    long rem = idx - z * (long)LS * DD;
    long j = rem / DD, d = rem - j * DD;
    long b = z >> 3, h = z & 7;
    g_Sk[idx] = (j < NN_) ? g_skv[(b * NN_ + j) * (2 * INNER_) + h * DD + d]
                          : SQRT_D * Sm_k[h * (MTOK * DD) + (j - NN_) * DD + d];
}

__global__ void pack_SvT(const float* __restrict__ Sm_v)
{
    long idx = (long)blockIdx.x * blockDim.x + threadIdx.x;
    const long total = (long)BB * HH * DD * LS;
    if (idx >= total) return;
    long z = idx / ((long)DD * LS);
    long rem = idx - z * (long)DD * LS;
    long d = rem / LS, j = rem - d * LS;
    long b = z >> 3, h = z & 7;
    g_SvT[idx] = (j < NN_) ? g_skv[(b * NN_ + j) * (2 * INNER_) + INNER_ + h * DD + d]
                           : SQRT_M * Sm_v[h * (MTOK * DD) + (j - NN_) * DD + d];
}

__global__ void pack_out()
{
    long idx = (long)blockIdx.x * blockDim.x + threadIdx.x;
    const long total = (long)BB * NN_ * INNER_;
    if (idx >= total) return;
    long b = idx / ((long)NN_ * INNER_);
    long rem = idx - b * (long)NN_ * INNER_;
    long n = rem / INNER_;
    long c = rem - n * INNER_;
    long h = c / DD, d = c - h * DD;
    g_out[idx] = g_obh[((b * HH + h) * NN_ + n) * DD + d];
}

// ---------------- launch ----------------
static inline dim3 eltGrid(long n) { return dim3((unsigned)((n + 255) / 256)); }
static inline unsigned cdiv(int a, int b) { return (unsigned)((a + b - 1) / b); }

extern "C" void kernel_launch(void* const* d_in, const int* in_sizes, int n_in,
                              void* d_out, int out_size)
{
    const float* inp  = (const float*)d_in[0];
    const float* x    = (const float*)d_in[1];
    const float* y    = (const float*)d_in[2];
    const float* Wq   = (const float*)d_in[3];
    const float* bq   = (const float*)d_in[4];
    const float* Wkv  = (const float*)d_in[5];
    const float* bkv  = (const float*)d_in[6];
    const float* Wf   = (const float*)d_in[7];
    const float* bf   = (const float*)d_in[8];
    const float* Wo   = (const float*)d_in[9];
    const float* bo   = (const float*)d_in[10];
    const float* m_k  = (const float*)d_in[11];
    // d_in[12] = m_v : unused (cross-attention v never feeds the output)
    const float* Sm_k = (const float*)d_in[13];
    const float* Sm_v = (const float*)d_in[14];
    float* out = (float*)d_out;

    float* p_ctx;  cudaGetSymbolAddress((void**)&p_ctx,  g_ctx);
    float* p_kctx; cudaGetSymbolAddress((void**)&p_kctx, g_kctx);
    float* p_skv;  cudaGetSymbolAddress((void**)&p_skv,  g_skv);
    float* p_qlin; cudaGetSymbolAddress((void**)&p_qlin, g_qlin);
    float* p_Q;    cudaGetSymbolAddress((void**)&p_Q,    g_Q);
    float* p_K;    cudaGetSymbolAddress((void**)&p_K,    g_K);
    float* p_Sk;   cudaGetSymbolAddress((void**)&p_Sk,   g_Sk);
    float* p_SvT;  cudaGetSymbolAddress((void**)&p_SvT,  g_SvT);
    float* p_P;    cudaGetSymbolAddress((void**)&p_P,    g_P);
    float* p_S2;   cudaGetSymbolAddress((void**)&p_S2,   g_S2);
    float* p_obh;  cudaGetSymbolAddress((void**)&p_obh,  g_obh);
    float* p_out;  cudaGetSymbolAddress((void**)&p_out,  g_out);

    // 1. context = concat(x, y)
    pack_ctx<<<eltGrid((long)CTX * BB * DIM_), 256>>>(x, y);

    // 2. q_lin = inp @ Wq^T + bq   [8192, 512]
    gemm_nt<<<dim3(cdiv(INNER_, BN), cdiv(BB * NN_, BM), 1), 256>>>(
        inp, DIM_, 0, Wq, DIM_, 0, bq, nullptr, 0, 0,
        p_qlin, INNER_, 0, BB * NN_, INNER_, DIM_, 1.0f);

    // 3. k_ctx = context @ Wkv[0:512]^T + bkv[0:512]   [16384, 512]  (v half is dead)
    gemm_nt<<<dim3(cdiv(INNER_, BN), cdiv(BB * CTX, BM), 1), 256>>>(
        p_ctx, DIM_, 0, Wkv, DIM_, 0, bkv, nullptr, 0, 0,
        p_kctx, INNER_, 0, BB * CTX, INNER_, DIM_, 1.0f);

    // 4. skv = inp @ Wkv^T + bkv   [8192, 1024]
    gemm_nt<<<dim3(cdiv(2 * INNER_, BN), cdiv(BB * NN_, BM), 1), 256>>>(
        inp, DIM_, 0, Wkv, DIM_, 0, bkv, nullptr, 0, 0,
        p_skv, 2 * INNER_, 0, BB * NN_, 2 * INNER_, DIM_, 1.0f);

    // 5. head-split packs (+ memory tokens)
    pack_Q  <<<eltGrid((long)BB * HH * NN_ * DD), 256>>>();
    pack_K  <<<eltGrid((long)BB * HH * LK * DD), 256>>>(m_k);
    pack_Sk <<<eltGrid((long)BB * HH * LS * DD), 256>>>(Sm_k);
    pack_SvT<<<eltGrid((long)BB * HH * DD * LS), 256>>>(Sm_v);

    // 6. cross scores: P[z] = SCALE * Q[z] @ K[z]^T    [64 x 1024 x 2051]
    gemm_nt<<<dim3(cdiv(LK, BN), cdiv(NN_, BM), BB * HH), 256>>>(
        p_Q, DD, (long)NN_ * DD, p_K, DD, (long)LK * DD, nullptr, nullptr, 0, 0,
        p_P, LK, (long)NN_ * LK, NN_, LK, DD, SCALE_);

    //    self scores: S2[z] = SCALE * Q[z] @ Sk[z]^T   [64 x 1024 x 1027]
    gemm_nt<<<dim3(cdiv(LS, BN), cdiv(NN_, BM), BB * HH), 256>>>(
        p_Q, DD, (long)NN_ * DD, p_Sk, DD, (long)LS * DD, nullptr, nullptr, 0, 0,
        p_S2, LS, (long)NN_ * LS, NN_, LS, DD, SCALE_);

    // 7. softmax
    softmax_rows<<<BB * HH * NN_, 256>>>(p_P, LK);
    softmax_rows<<<BB * HH * NN_, 256>>>(p_S2, LS);

    // 8. attn = P @ Wf^T + bf + S2, written IN-PLACE into S2
    //    (flat M=65536, N=1027, K=2051) — dominant GEMM, 276 GFLOP
    gemm_nt<<<dim3(cdiv(LS, BN), cdiv(BB * HH * NN_, BM), 1), 256>>>(
        p_P, LK, 0, Wf, LK, 0, bf, p_S2, LS, 0,
        p_S2, LS, 0, BB * HH * NN_, LS, LK, 1.0f);

    // 9. obh[z] = attn[z] @ SvT[z]^T   [64 x 1024 x 64]
    gemm_nt<<<dim3(cdiv(DD, BN), cdiv(NN_, BM), BB * HH), 256>>>(
        p_S2, LS, (long)NN_ * LS, p_SvT, LS, (long)DD * LS, nullptr, nullptr, 0, 0,
        p_obh, DD, (long)NN_ * DD, NN_, DD, LS, 1.0f);

    // 10. merge heads
    pack_out<<<eltGrid((long)BB * NN_ * INNER_), 256>>>();

    // 11. final = out @ Wo^T + bo   [8192, 512]
    gemm_nt<<<dim3(cdiv(DIM_, BN), cdiv(BB * NN_, BM), 1), 256>>>(
        p_out, INNER_, 0, Wo, INNER_, 0, bo, nullptr, 0, 0,
        out, DIM_, 0, BB * NN_, DIM_, INNER_, 1.0f);
}

// round 6
// speedup vs baseline: 6.8748x; 2.1284x over previous
#include <cuda_runtime.h>
#include <math.h>

// ---------------- problem constants ----------------
#define BB      8
#define NN_     1024
#define DIM_    512
#define HH      8
#define DD      64
#define INNER_  512
#define MTOK    3
#define CTX     2048            // 2*N
#define LK      2051            // 2N + M
#define LS      1027            // N + M
#define SCALE_  0.125f          // 64^-0.5
#define SQRT_D  8.0f
#define SQRT_M  1.7320508075688772f
#define ZZ      (BB * HH)       // 64

// ---------------- scratch (device globals; no allocation allowed) ----------------
__device__ float g_ctx  [CTX * BB * DIM_];          // 32 MB
__device__ float g_kctx [CTX * BB * INNER_];        // 32 MB
__device__ float g_skv  [BB * NN_ * 2 * INNER_];    // 32 MB
__device__ float g_qlin [BB * NN_ * INNER_];        // 16 MB
__device__ float g_Q    [BB * HH * NN_ * DD];       // 16 MB
__device__ float g_K    [BB * HH * LK * DD];        // 67 MB
__device__ float g_Sk   [BB * HH * LS * DD];        // 34 MB
__device__ float g_SvT  [BB * HH * DD * LS];        // 34 MB
__device__ float g_P    [(size_t)BB * HH * NN_ * LK];  // 537 MB
__device__ float g_S2   [(size_t)BB * HH * NN_ * LS];  // 269 MB
__device__ float g_WfT  [LK * LS];                  // 8.4 MB  (Wf transposed)
__device__ float g_Gt   [ZZ * DD * LK];             // 33.6 MB (G^T per head: [z, d, k])
__device__ float g_cvec [ZZ * DD];                  // bf @ Sv per head
__device__ float g_obh  [BB * HH * NN_ * DD];       // 16 MB
__device__ float g_out  [BB * NN_ * INNER_];        // 16 MB

// ---------------- fast NT SGEMM: C = alpha*(A @ W^T) + bias + bias2_z + add ----------------
// A: [M,K] row-major (lda), W: [N,K] row-major (ldw), C: [M,N] (ldc)
// batched via blockIdx.z with strides sA/sW/sC/sAdd/sB2.
// bias2: z-strided per-column vector (broadcast over rows).
// In-place C == addm is safe (each element read once by its own writer thread).
#define BM 128
#define BN 128
#define BK 8

__global__ __launch_bounds__(256, 2)
void gemm_nt(const float* __restrict__ A, int lda, long sA,
             const float* __restrict__ W, int ldw, long sW,
             const float* __restrict__ bias,
             const float* __restrict__ bias2, long sB2,
             const float* __restrict__ addm, int ldadd, long sAdd,
             float* __restrict__ C, int ldc, long sC,
             int M, int N, int K, float alpha)
{
    __shared__ float As[2][BK][BM];
    __shared__ float Bs[2][BK][BN];

    const long bz = blockIdx.z;
    const float* Ab   = A + bz * sA;
    const float* Wb   = W + bz * sW;
    const float* Addb = addm ? (addm + bz * sAdd) : nullptr;
    const float* B2b  = bias2 ? (bias2 + bz * sB2) : nullptr;
    float* Cb = C + bz * sC;

    const int row0 = blockIdx.y * BM;
    const int col0 = blockIdx.x * BN;
    const int tid  = threadIdx.x;
    const int tx   = tid & 15;       // 0..15 -> output cols
    const int ty   = tid >> 4;       // 0..15 -> output rows

    // global->smem load mapping: each thread loads 4 consecutive k for one row
    const int ldRow = tid >> 1;          // 0..127
    const int ldK   = (tid & 1) * 4;     // 0 or 4
    const int gr = row0 + ldRow;         // A row
    const int gn = col0 + ldRow;         // W row (= C col)

    float acc[8][8] = {};
    float ra[4], rb[4];

    // ---- preload tile 0 ----
    #pragma unroll
    for (int i = 0; i < 4; i++) {
        int gk = ldK + i;
        ra[i] = (gr < M && gk < K) ? Ab[(long)gr * lda + gk] : 0.0f;
        rb[i] = (gn < N && gk < K) ? Wb[(long)gn * ldw + gk] : 0.0f;
    }
    #pragma unroll
    for (int i = 0; i < 4; i++) {
        As[0][ldK + i][ldRow] = ra[i];
        Bs[0][ldK + i][ldRow] = rb[i];
    }
    __syncthreads();

    int buf = 0;
    for (int k0 = 0; k0 < K; k0 += BK) {
        const int k1 = k0 + BK;
        // prefetch next tile into registers (overlaps with compute)
        if (k1 < K) {
            #pragma unroll
            for (int i = 0; i < 4; i++) {
                int gk = k1 + ldK + i;
                ra[i] = (gr < M && gk < K) ? Ab[(long)gr * lda + gk] : 0.0f;
                rb[i] = (gn < N && gk < K) ? Wb[(long)gn * ldw + gk] : 0.0f;
            }
        }

        // compute on current buffer
        #pragma unroll
        for (int kk = 0; kk < BK; kk++) {
            float4 a0 = *reinterpret_cast<const float4*>(&As[buf][kk][ty * 4]);
            float4 a1 = *reinterpret_cast<const float4*>(&As[buf][kk][ty * 4 + 64]);
            float4 b0 = *reinterpret_cast<const float4*>(&Bs[buf][kk][tx * 4]);
            float4 b1 = *reinterpret_cast<const float4*>(&Bs[buf][kk][tx * 4 + 64]);
            float a[8] = {a0.x, a0.y, a0.z, a0.w, a1.x, a1.y, a1.z, a1.w};
            float b[8] = {b0.x, b0.y, b0.z, b0.w, b1.x, b1.y, b1.z, b1.w};
            #pragma unroll
            for (int i = 0; i < 8; i++)
                #pragma unroll
                for (int j = 0; j < 8; j++)
                    acc[i][j] = fmaf(a[i], b[j], acc[i][j]);
        }

        if (k1 < K) {
            #pragma unroll
            for (int i = 0; i < 4; i++) {
                As[buf ^ 1][ldK + i][ldRow] = ra[i];
                Bs[buf ^ 1][ldK + i][ldRow] = rb[i];
            }
            __syncthreads();
            buf ^= 1;
        }
    }

    // ---- fused epilogue ----
    #pragma unroll
    for (int i = 0; i < 8; i++) {
        int r = row0 + ((i < 4) ? (ty * 4 + i) : (64 + ty * 4 + i - 4));
        if (r >= M) continue;
        #pragma unroll
        for (int j = 0; j < 8; j++) {
            int c = col0 + ((j < 4) ? (tx * 4 + j) : (64 + tx * 4 + j - 4));
            if (c >= N) continue;
            float v = alpha * acc[i][j];
            if (bias) v += bias[c];
            if (B2b)  v += B2b[c];
            if (Addb) v += Addb[(long)r * ldadd + c];
            Cb[(long)r * ldc + c] = v;
        }
    }
}

// ---------------- row softmax (one block per row) ----------------
__global__ __launch_bounds__(256)
void softmax_rows(float* __restrict__ data, int cols)
{
    const long row = blockIdx.x;
    float* p = data + row * (long)cols;
    const int tid = threadIdx.x;
    __shared__ float sh[256];

    float mx = -3.0e38f;
    for (int c = tid; c < cols; c += 256) mx = fmaxf(mx, p[c]);
    sh[tid] = mx; __syncthreads();
    for (int s = 128; s > 0; s >>= 1) {
        if (tid < s) sh[tid] = fmaxf(sh[tid], sh[tid + s]);
        __syncthreads();
    }
    mx = sh[0]; __syncthreads();

    float sum = 0.0f;
    for (int c = tid; c < cols; c += 256) {
        float e = __expf(p[c] - mx);
        p[c] = e;
        sum += e;
    }
    sh[tid] = sum; __syncthreads();
    for (int s = 128; s > 0; s >>= 1) {
        if (tid < s) sh[tid] += sh[tid + s];
        __syncthreads();
    }
    float inv = 1.0f / sh[0];
    for (int c = tid; c < cols; c += 256) p[c] *= inv;
}

// ---------------- pack kernels ----------------
__global__ void pack_ctx(const float* __restrict__ x, const float* __restrict__ y)
{
    long idx = (long)blockIdx.x * blockDim.x + threadIdx.x;
    const long total = (long)CTX * BB * DIM_;
    if (idx >= total) return;
    long b = idx / ((long)CTX * DIM_);
    long rem = idx - b * (long)CTX * DIM_;
    long j = rem / DIM_;
    long c = rem - j * DIM_;
    g_ctx[idx] = (j < NN_) ? x[(b * NN_ + j) * DIM_ + c]
                           : y[(b * NN_ + (j - NN_)) * DIM_ + c];
}

__global__ void pack_Q()
{
    long idx = (long)blockIdx.x * blockDim.x + threadIdx.x;
    const long total = (long)BB * HH * NN_ * DD;
    if (idx >= total) return;
    long z = idx / ((long)NN_ * DD);
    long rem = idx - z * (long)NN_ * DD;
    long n = rem / DD, d = rem - n * DD;
    long b = z >> 3, h = z & 7;
    g_Q[idx] = g_qlin[(b * NN_ + n) * INNER_ + h * DD + d];
}

__global__ void pack_K(const float* __restrict__ m_k)
{
    long idx = (long)blockIdx.x * blockDim.x + threadIdx.x;
    const long total = (long)BB * HH * LK * DD;
    if (idx >= total) return;
    long z = idx / ((long)LK * DD);
    long rem = idx - z * (long)LK * DD;
    long j = rem / DD, d = rem - j * DD;
    long b = z >> 3, h = z & 7;
    g_K[idx] = (j < CTX) ? g_kctx[(b * CTX + j) * INNER_ + h * DD + d]
                         : SQRT_D * m_k[h * (MTOK * DD) + (j - CTX) * DD + d];
}

__global__ void pack_Sk(const float* __restrict__ Sm_k)
{
    long idx = (long)blockIdx.x * blockDim.x + threadIdx.x;
    const long total = (long)BB * HH * LS * DD;
    if (idx >= total) return;
    long z = idx / ((long)LS * DD);
    long rem = idx - z * (long)LS * DD;
    long j = rem / DD, d = rem - j * DD;
    long b = z >> 3, h = z & 7;
    g_Sk[idx] = (j < NN_) ? g_skv[(b * NN_ + j) * (2 * INNER_) + h * DD + d]
                          : SQRT_D * Sm_k[h * (MTOK * DD) + (j - NN_) * DD + d];
}

__global__ void pack_SvT(const float* __restrict__ Sm_v)
{
    long idx = (long)blockIdx.x * blockDim.x + threadIdx.x;
    const long total = (long)BB * HH * DD * LS;
    if (idx >= total) return;
    long z = idx / ((long)DD * LS);
    long rem = idx - z * (long)DD * LS;
    long d = rem / LS, j = rem - d * LS;
    long b = z >> 3, h = z & 7;
    g_SvT[idx] = (j < NN_) ? g_skv[(b * NN_ + j) * (2 * INNER_) + INNER_ + h * DD + d]
                           : SQRT_M * Sm_v[h * (MTOK * DD) + (j - NN_) * DD + d];
}

// WfT[k, o] = Wf[o, k]   (Wf: [LS, LK] row-major -> WfT: [LK, LS] row-major)
__global__ void transpose_Wf(const float* __restrict__ Wf)
{
    long idx = (long)blockIdx.x * blockDim.x + threadIdx.x;
    const long total = (long)LK * LS;
    if (idx >= total) return;
    long k = idx / LS, o = idx - k * LS;
    g_WfT[idx] = Wf[o * (long)LK + k];
}

// cvec[z, d] = sum_o bf[o] * SvT[z, d, o]   (one warp per (z,d))
__global__ void calc_cvec(const float* __restrict__ bf)
{
    int warp = (blockIdx.x * blockDim.x + threadIdx.x) >> 5;
    int lane = threadIdx.x & 31;
    if (warp >= ZZ * DD) return;
    const float* sv = g_SvT + (long)warp * LS;
    float s = 0.0f;
    for (int o = lane; o < LS; o += 32) s += bf[o] * sv[o];
    #pragma unroll
    for (int sft = 16; sft > 0; sft >>= 1)
        s += __shfl_xor_sync(0xFFFFFFFF, s, sft);
    if (lane == 0) g_cvec[warp] = s;
}

__global__ void pack_out()
{
    long idx = (long)blockIdx.x * blockDim.x + threadIdx.x;
    const long total = (long)BB * NN_ * INNER_;
    if (idx >= total) return;
    long b = idx / ((long)NN_ * INNER_);
    long rem = idx - b * (long)NN_ * INNER_;
    long n = rem / INNER_;
    long c = rem - n * INNER_;
    long h = c / DD, d = c - h * DD;
    g_out[idx] = g_obh[((b * HH + h) * NN_ + n) * DD + d];
}

// ---------------- launch ----------------
static inline dim3 eltGrid(long n) { return dim3((unsigned)((n + 255) / 256)); }
static inline unsigned cdiv(int a, int b) { return (unsigned)((a + b - 1) / b); }

extern "C" void kernel_launch(void* const* d_in, const int* in_sizes, int n_in,
                              void* d_out, int out_size)
{
    const float* inp  = (const float*)d_in[0];
    const float* x    = (const float*)d_in[1];
    const float* y    = (const float*)d_in[2];
    const float* Wq   = (const float*)d_in[3];
    const float* bq   = (const float*)d_in[4];
    const float* Wkv  = (const float*)d_in[5];
    const float* bkv  = (const float*)d_in[6];
    const float* Wf   = (const float*)d_in[7];
    const float* bf   = (const float*)d_in[8];
    const float* Wo   = (const float*)d_in[9];
    const float* bo   = (const float*)d_in[10];
    const float* m_k  = (const float*)d_in[11];
    // d_in[12] = m_v : unused (cross-attention v never feeds the output)
    const float* Sm_k = (const float*)d_in[13];
    const float* Sm_v = (const float*)d_in[14];
    float* out = (float*)d_out;

    float* p_ctx;  cudaGetSymbolAddress((void**)&p_ctx,  g_ctx);
    float* p_kctx; cudaGetSymbolAddress((void**)&p_kctx, g_kctx);
    float* p_skv;  cudaGetSymbolAddress((void**)&p_skv,  g_skv);
    float* p_qlin; cudaGetSymbolAddress((void**)&p_qlin, g_qlin);
    float* p_Q;    cudaGetSymbolAddress((void**)&p_Q,    g_Q);
    float* p_K;    cudaGetSymbolAddress((void**)&p_K,    g_K);
    float* p_Sk;   cudaGetSymbolAddress((void**)&p_Sk,   g_Sk);
    float* p_SvT;  cudaGetSymbolAddress((void**)&p_SvT,  g_SvT);
    float* p_P;    cudaGetSymbolAddress((void**)&p_P,    g_P);
    float* p_S2;   cudaGetSymbolAddress((void**)&p_S2,   g_S2);
    float* p_WfT;  cudaGetSymbolAddress((void**)&p_WfT,  g_WfT);
    float* p_Gt;   cudaGetSymbolAddress((void**)&p_Gt,   g_Gt);
    float* p_cvec; cudaGetSymbolAddress((void**)&p_cvec, g_cvec);
    float* p_obh;  cudaGetSymbolAddress((void**)&p_obh,  g_obh);
    float* p_out;  cudaGetSymbolAddress((void**)&p_out,  g_out);

    // 1. context = concat(x, y)
    pack_ctx<<<eltGrid((long)CTX * BB * DIM_), 256>>>(x, y);

    // 2. q_lin = inp @ Wq^T + bq   [8192, 512]
    gemm_nt<<<dim3(cdiv(INNER_, BN), cdiv(BB * NN_, BM), 1), 256>>>(
        inp, DIM_, 0, Wq, DIM_, 0, bq, nullptr, 0, nullptr, 0, 0,
        p_qlin, INNER_, 0, BB * NN_, INNER_, DIM_, 1.0f);

    // 3. k_ctx = context @ Wkv[0:512]^T + bkv[0:512]   [16384, 512]  (v half is dead)
    gemm_nt<<<dim3(cdiv(INNER_, BN), cdiv(BB * CTX, BM), 1), 256>>>(
        p_ctx, DIM_, 0, Wkv, DIM_, 0, bkv, nullptr, 0, nullptr, 0, 0,
        p_kctx, INNER_, 0, BB * CTX, INNER_, DIM_, 1.0f);

    // 4. skv = inp @ Wkv^T + bkv   [8192, 1024]
    gemm_nt<<<dim3(cdiv(2 * INNER_, BN), cdiv(BB * NN_, BM), 1), 256>>>(
        inp, DIM_, 0, Wkv, DIM_, 0, bkv, nullptr, 0, nullptr, 0, 0,
        p_skv, 2 * INNER_, 0, BB * NN_, 2 * INNER_, DIM_, 1.0f);

    // 5. head-split packs (+ memory tokens) and Wf transpose
    pack_Q  <<<eltGrid((long)BB * HH * NN_ * DD), 256>>>();
    pack_K  <<<eltGrid((long)BB * HH * LK * DD), 256>>>(m_k);
    pack_Sk <<<eltGrid((long)BB * HH * LS * DD), 256>>>(Sm_k);
    pack_SvT<<<eltGrid((long)BB * HH * DD * LS), 256>>>(Sm_v);
    transpose_Wf<<<eltGrid((long)LK * LS), 256>>>(Wf);
    calc_cvec<<<cdiv(ZZ * DD * 32, 256), 256>>>(bf);

    // 6. cross scores: P[z] = SCALE * Q[z] @ K[z]^T    [64 x 1024 x 2051]
    gemm_nt<<<dim3(cdiv(LK, BN), cdiv(NN_, BM), ZZ), 256>>>(
        p_Q, DD, (long)NN_ * DD, p_K, DD, (long)LK * DD,
        nullptr, nullptr, 0, nullptr, 0, 0,
        p_P, LK, (long)NN_ * LK, NN_, LK, DD, SCALE_);

    //    self scores: S2[z] = SCALE * Q[z] @ Sk[z]^T   [64 x 1024 x 1027]
    gemm_nt<<<dim3(cdiv(LS, BN), cdiv(NN_, BM), ZZ), 256>>>(
        p_Q, DD, (long)NN_ * DD, p_Sk, DD, (long)LS * DD,
        nullptr, nullptr, 0, nullptr, 0, 0,
        p_S2, LS, (long)NN_ * LS, NN_, LS, DD, SCALE_);

    // 7. softmax
    softmax_rows<<<ZZ * NN_, 256>>>(p_P, LK);
    softmax_rows<<<ZZ * NN_, 256>>>(p_S2, LS);

    // 8a. Gt[z] = SvT[z] @ WfT^T  -> Gt[z][d,k] = sum_o Sv[o,d]*Wf[o,k]
    //     [64 batches: M=64, N=2051, K=1027]   (replaces the 276 GFLOP GEMM!)
    gemm_nt<<<dim3(cdiv(LK, BN), cdiv(DD, BM), ZZ), 256>>>(
        p_SvT, LS, (long)DD * LS, p_WfT, LS, 0,
        nullptr, nullptr, 0, nullptr, 0, 0,
        p_Gt, LK, (long)DD * LK, DD, LK, LS, 1.0f);

    // 8b. obh[z] = S2[z] @ Sv[z]  (= S2 @ SvT^T)   [64 x 1024 x 64]
    gemm_nt<<<dim3(cdiv(DD, BN), cdiv(NN_, BM), ZZ), 256>>>(
        p_S2, LS, (long)NN_ * LS, p_SvT, LS, (long)DD * LS,
        nullptr, nullptr, 0, nullptr, 0, 0,
        p_obh, DD, (long)NN_ * DD, NN_, DD, LS, 1.0f);

    // 8c. obh[z] += P[z] @ Gt[z]^T + cvec[z]  (in-place accumulate)
    //     [64 x 1024 x 64, K=2051]
    gemm_nt<<<dim3(cdiv(DD, BN), cdiv(NN_, BM), ZZ), 256>>>(
        p_P, LK, (long)NN_ * LK, p_Gt, LK, (long)DD * LK,
        nullptr, p_cvec, DD, p_obh, DD, (long)NN_ * DD,
        p_obh, DD, (long)NN_ * DD, NN_, DD, LK, 1.0f);

    // 9. merge heads
    pack_out<<<eltGrid((long)BB * NN_ * INNER_), 256>>>();

    // 10. final = out @ Wo^T + bo   [8192, 512]
    gemm_nt<<<dim3(cdiv(DIM_, BN), cdiv(BB * NN_, BM), 1), 256>>>(
        p_out, INNER_, 0, Wo, INNER_, 0, bo, nullptr, 0, nullptr, 0, 0,
        out, DIM_, 0, BB * NN_, DIM_, INNER_, 1.0f);
}

// round 8
// speedup vs baseline: 7.7186x; 1.1227x over previous
#include <cuda_runtime.h>
#include <math.h>

// ---------------- problem constants ----------------
#define BB      8
#define NN_     1024
#define DIM_    512
#define HH      8
#define DD      64
#define INNER_  512
#define MTOK    3
#define CTX     2048            // 2*N
#define LK      2051            // 2N + M
#define LS      1027            // N + M
#define SCALE_  0.125f          // 64^-0.5
#define SQRT_D  8.0f
#define SQRT_M  1.7320508075688772f
#define ZZ      (BB * HH)       // 64

// ---------------- scratch (device globals; no allocation allowed) ----------------
__device__ float g_ctx  [CTX * BB * DIM_];          // 32 MB
__device__ float g_kctx [CTX * BB * INNER_];        // 32 MB
__device__ float g_skv  [BB * NN_ * 2 * INNER_];    // 32 MB
__device__ float g_qlin [BB * NN_ * INNER_];        // 16 MB
__device__ float g_Q    [BB * HH * NN_ * DD];       // 16 MB
__device__ float g_K    [BB * HH * LK * DD];        // 67 MB
__device__ float g_Sk   [BB * HH * LS * DD];        // 34 MB
__device__ float g_SvT  [BB * HH * DD * LS];        // 34 MB
__device__ float g_P    [(size_t)BB * HH * NN_ * LK];  // 537 MB
__device__ float g_S2   [(size_t)BB * HH * NN_ * LS];  // 269 MB
__device__ float g_WfT  [LK * LS];                  // 8.4 MB  (Wf transposed)
__device__ float g_Gt   [ZZ * DD * LK];             // 33.6 MB (G^T per head: [z, d, k])
__device__ float g_cvec [ZZ * DD];                  // bf @ Sv per head
__device__ float g_obh  [BB * HH * NN_ * DD];       // 16 MB
__device__ float g_out  [BB * NN_ * INNER_];        // 16 MB

// ---------------- templated NT SGEMM: C = alpha*(A @ W^T) + bias + bias2_z + add ----
// A: [M,K] row-major (lda), W: [N,K] row-major (ldw), C: [M,N] (ldc)
// batched via blockIdx.z with strides sA/sW/sC/sAdd/sB2.
// Tile BMt x BNt x 8, 256 threads, (BMt/16)x(BNt/16) micro-tile, double-buffered.
// In-place C == addm is safe (each element read once by its own writer thread).
#define BK 8

template<int BMt, int BNt>
__global__ __launch_bounds__(256, 2)
void gemm_t(const float* __restrict__ A, int lda, long sA,
            const float* __restrict__ W, int ldw, long sW,
            const float* __restrict__ bias,
            const float* __restrict__ bias2, long sB2,
            const float* __restrict__ addm, int ldadd, long sAdd,
            float* __restrict__ C, int ldc, long sC,
            int M, int N, int K, float alpha)
{
    constexpr int RM = BMt / 16;           // rows per thread (4 or 8)
    constexpr int RN = BNt / 16;           // cols per thread (4 or 8)
    constexpr int LA = BMt / 32;           // A floats loaded per thread (2 or 4)
    constexpr int LB = BNt / 32;           // B floats loaded per thread
    constexpr int TPR_A = BK / LA;         // threads per A row (2 or 4)
    constexpr int TPR_B = BK / LB;

    __shared__ float As[2][BK][BMt];
    __shared__ float Bs[2][BK][BNt];

    const long bz = blockIdx.z;
    const float* Ab   = A + bz * sA;
    const float* Wb   = W + bz * sW;
    const float* Addb = addm ? (addm + bz * sAdd) : nullptr;
    const float* B2b  = bias2 ? (bias2 + bz * sB2) : nullptr;
    float* Cb = C + bz * sC;

    const int row0 = blockIdx.y * BMt;
    const int col0 = blockIdx.x * BNt;
    const int tid  = threadIdx.x;
    const int tx   = tid & 15;
    const int ty   = tid >> 4;

    const int ldRowA = tid / TPR_A;
    const int ldKA   = (tid % TPR_A) * LA;
    const int ldRowB = tid / TPR_B;
    const int ldKB   = (tid % TPR_B) * LB;
    const int gr = row0 + ldRowA;          // A row
    const int gn = col0 + ldRowB;          // W row (= C col)

    float acc[RM][RN] = {};
    float ra[LA], rb[LB];

    // ---- preload tile 0 ----
    #pragma unroll
    for (int i = 0; i < LA; i++) {
        int gk = ldKA + i;
        ra[i] = (gr < M && gk < K) ? Ab[(long)gr * lda + gk] : 0.0f;
    }
    #pragma unroll
    for (int i = 0; i < LB; i++) {
        int gk = ldKB + i;
        rb[i] = (gn < N && gk < K) ? Wb[(long)gn * ldw + gk] : 0.0f;
    }
    #pragma unroll
    for (int i = 0; i < LA; i++) As[0][ldKA + i][ldRowA] = ra[i];
    #pragma unroll
    for (int i = 0; i < LB; i++) Bs[0][ldKB + i][ldRowB] = rb[i];
    __syncthreads();

    int buf = 0;
    for (int k0 = 0; k0 < K; k0 += BK) {
        const int k1 = k0 + BK;
        if (k1 < K) {
            #pragma unroll
            for (int i = 0; i < LA; i++) {
                int gk = k1 + ldKA + i;
                ra[i] = (gr < M && gk < K) ? Ab[(long)gr * lda + gk] : 0.0f;
            }
            #pragma unroll
            for (int i = 0; i < LB; i++) {
                int gk = k1 + ldKB + i;
                rb[i] = (gn < N && gk < K) ? Wb[(long)gn * ldw + gk] : 0.0f;
            }
        }

        #pragma unroll
        for (int kk = 0; kk < BK; kk++) {
            float a[RM], b[RN];
            #pragma unroll
            for (int g = 0; g < RM / 4; g++) {
                float4 v = *reinterpret_cast<const float4*>(&As[buf][kk][g * 64 + ty * 4]);
                a[g * 4 + 0] = v.x; a[g * 4 + 1] = v.y;
                a[g * 4 + 2] = v.z; a[g * 4 + 3] = v.w;
            }
            #pragma unroll
            for (int g = 0; g < RN / 4; g++) {
                float4 v = *reinterpret_cast<const float4*>(&Bs[buf][kk][g * 64 + tx * 4]);
                b[g * 4 + 0] = v.x; b[g * 4 + 1] = v.y;
                b[g * 4 + 2] = v.z; b[g * 4 + 3] = v.w;
            }
            #pragma unroll
            for (int i = 0; i < RM; i++)
                #pragma unroll
                for (int j = 0; j < RN; j++)
                    acc[i][j] = fmaf(a[i], b[j], acc[i][j]);
        }

        if (k1 < K) {
            #pragma unroll
            for (int i = 0; i < LA; i++) As[buf ^ 1][ldKA + i][ldRowA] = ra[i];
            #pragma unroll
            for (int i = 0; i < LB; i++) Bs[buf ^ 1][ldKB + i][ldRowB] = rb[i];
            __syncthreads();
            buf ^= 1;
        }
    }

    // ---- fused epilogue ----
    #pragma unroll
    for (int i = 0; i < RM; i++) {
        int r = row0 + (i / 4) * 64 + ty * 4 + (i % 4);
        if (r >= M) continue;
        #pragma unroll
        for (int j = 0; j < RN; j++) {
            int c = col0 + (j / 4) * 64 + tx * 4 + (j % 4);
            if (c >= N) continue;
            float v = alpha * acc[i][j];
            if (bias) v += bias[c];
            if (B2b)  v += B2b[c];
            if (Addb) v += Addb[(long)r * ldadd + c];
            Cb[(long)r * ldc + c] = v;
        }
    }
}

// ---------------- row softmax (one block per row) ----------------
__global__ __launch_bounds__(256)
void softmax_rows(float* __restrict__ data, int cols)
{
    const long row = blockIdx.x;
    float* p = data + row * (long)cols;
    const int tid = threadIdx.x;
    __shared__ float sh[256];

    float mx = -3.0e38f;
    for (int c = tid; c < cols; c += 256) mx = fmaxf(mx, p[c]);
    sh[tid] = mx; __syncthreads();
    for (int s = 128; s > 0; s >>= 1) {
        if (tid < s) sh[tid] = fmaxf(sh[tid], sh[tid + s]);
        __syncthreads();
    }
    mx = sh[0]; __syncthreads();

    float sum = 0.0f;
    for (int c = tid; c < cols; c += 256) {
        float e = __expf(p[c] - mx);
        p[c] = e;
        sum += e;
    }
    sh[tid] = sum; __syncthreads();
    for (int s = 128; s > 0; s >>= 1) {
        if (tid < s) sh[tid] += sh[tid + s];
        __syncthreads();
    }
    float inv = 1.0f / sh[0];
    for (int c = tid; c < cols; c += 256) p[c] *= inv;
}

// ---------------- pack kernels ----------------
__global__ void pack_ctx(const float* __restrict__ x, const float* __restrict__ y)
{
    long idx = (long)blockIdx.x * blockDim.x + threadIdx.x;
    const long total = (long)CTX * BB * DIM_;
    if (idx >= total) return;
    long b = idx / ((long)CTX * DIM_);
    long rem = idx - b * (long)CTX * DIM_;
    long j = rem / DIM_;
    long c = rem - j * DIM_;
    g_ctx[idx] = (j < NN_) ? x[(b * NN_ + j) * DIM_ + c]
                           : y[(b * NN_ + (j - NN_)) * DIM_ + c];
}

__global__ void pack_Q()
{
    long idx = (long)blockIdx.x * blockDim.x + threadIdx.x;
    const long total = (long)BB * HH * NN_ * DD;
    if (idx >= total) return;
    long z = idx / ((long)NN_ * DD);
    long rem = idx - z * (long)NN_ * DD;
    long n = rem / DD, d = rem - n * DD;
    long b = z >> 3, h = z & 7;
    g_Q[idx] = g_qlin[(b * NN_ + n) * INNER_ + h * DD + d];
}

__global__ void pack_K(const float* __restrict__ m_k)
{
    long idx = (long)blockIdx.x * blockDim.x + threadIdx.x;
    const long total = (long)BB * HH * LK * DD;
    if (idx >= total) return;
    long z = idx / ((long)LK * DD);
    long rem = idx - z * (long)LK * DD;
    long j = rem / DD, d = rem - j * DD;
    long b = z >> 3, h = z & 7;
    g_K[idx] = (j < CTX) ? g_kctx[(b * CTX + j) * INNER_ + h * DD + d]
                         : SQRT_D * m_k[h * (MTOK * DD) + (j - CTX) * DD + d];
}

__global__ void pack_Sk(const float* __restrict__ Sm_k)
{
    long idx = (long)blockIdx.x * blockDim.x + threadIdx.x;
    const long total = (long)BB * HH * LS * DD;
    if (idx >= total) return;
    long z = idx / ((long)LS * DD);
    long rem = idx - z * (long)LS * DD;
    long j = rem / DD, d = rem - j * DD;
    long b = z >> 3, h = z & 7;
    g_Sk[idx] = (j < NN_) ? g_skv[(b * NN_ + j) * (2 * INNER_) + h * DD + d]
                          : SQRT_D * Sm_k[h * (MTOK * DD) + (j - NN_) * DD + d];
}

__global__ void pack_SvT(const float* __restrict__ Sm_v)
{
    long idx = (long)blockIdx.x * blockDim.x + threadIdx.x;
    const long total = (long)BB * HH * DD * LS;
    if (idx >= total) return;
    long z = idx / ((long)DD * LS);
    long rem = idx - z * (long)DD * LS;
    long d = rem / LS, j = rem - d * LS;
    long b = z >> 3, h = z & 7;
    g_SvT[idx] = (j < NN_) ? g_skv[(b * NN_ + j) * (2 * INNER_) + INNER_ + h * DD + d]
                           : SQRT_M * Sm_v[h * (MTOK * DD) + (j - NN_) * DD + d];
}

// WfT[k, o] = Wf[o, k]   (Wf: [LS, LK] row-major -> WfT: [LK, LS] row-major)
__global__ void transpose_Wf(const float* __restrict__ Wf)
{
    long idx = (long)blockIdx.x * blockDim.x + threadIdx.x;
    const long total = (long)LK * LS;
    if (idx >= total) return;
    long k = idx / LS, o = idx - k * LS;
    g_WfT[idx] = Wf[o * (long)LK + k];
}

// cvec[z, d] = sum_o bf[o] * SvT[z, d, o]   (one warp per (z,d))
__global__ void calc_cvec(const float* __restrict__ bf)
{
    int warp = (blockIdx.x * blockDim.x + threadIdx.x) >> 5;
    int lane = threadIdx.x & 31;
    if (warp >= ZZ * DD) return;
    const float* sv = g_SvT + (long)warp * LS;
    float s = 0.0f;
    for (int o = lane; o < LS; o += 32) s += bf[o] * sv[o];
    #pragma unroll
    for (int sft = 16; sft > 0; sft >>= 1)
        s += __shfl_xor_sync(0xFFFFFFFF, s, sft);
    if (lane == 0) g_cvec[warp] = s;
}

__global__ void pack_out()
{
    long idx = (long)blockIdx.x * blockDim.x + threadIdx.x;
    const long total = (long)BB * NN_ * INNER_;
    if (idx >= total) return;
    long b = idx / ((long)NN_ * INNER_);
    long rem = idx - b * (long)NN_ * INNER_;
    long n = rem / INNER_;
    long c = rem - n * INNER_;
    long h = c / DD, d = c - h * DD;
    g_out[idx] = g_obh[((b * HH + h) * NN_ + n) * DD + d];
}

// ---------------- launch ----------------
static inline dim3 eltGrid(long n) { return dim3((unsigned)((n + 255) / 256)); }
static inline unsigned cdiv(int a, int b) { return (unsigned)((a + b - 1) / b); }

extern "C" void kernel_launch(void* const* d_in, const int* in_sizes, int n_in,
                              void* d_out, int out_size)
{
    const float* inp  = (const float*)d_in[0];
    const float* x    = (const float*)d_in[1];
    const float* y    = (const float*)d_in[2];
    const float* Wq   = (const float*)d_in[3];
    const float* bq   = (const float*)d_in[4];
    const float* Wkv  = (const float*)d_in[5];
    const float* bkv  = (const float*)d_in[6];
    const float* Wf   = (const float*)d_in[7];
    const float* bf   = (const float*)d_in[8];
    const float* Wo   = (const float*)d_in[9];
    const float* bo   = (const float*)d_in[10];
    const float* m_k  = (const float*)d_in[11];
    // d_in[12] = m_v : unused (cross-attention v never feeds the output)
    const float* Sm_k = (const float*)d_in[13];
    const float* Sm_v = (const float*)d_in[14];
    float* out = (float*)d_out;

    float* p_ctx;  cudaGetSymbolAddress((void**)&p_ctx,  g_ctx);
    float* p_kctx; cudaGetSymbolAddress((void**)&p_kctx, g_kctx);
    float* p_skv;  cudaGetSymbolAddress((void**)&p_skv,  g_skv);
    float* p_qlin; cudaGetSymbolAddress((void**)&p_qlin, g_qlin);
    float* p_Q;    cudaGetSymbolAddress((void**)&p_Q,    g_Q);
    float* p_K;    cudaGetSymbolAddress((void**)&p_K,    g_K);
    float* p_Sk;   cudaGetSymbolAddress((void**)&p_Sk,   g_Sk);
    float* p_SvT;  cudaGetSymbolAddress((void**)&p_SvT,  g_SvT);
    float* p_P;    cudaGetSymbolAddress((void**)&p_P,    g_P);
    float* p_S2;   cudaGetSymbolAddress((void**)&p_S2,   g_S2);
    float* p_WfT;  cudaGetSymbolAddress((void**)&p_WfT,  g_WfT);
    float* p_Gt;   cudaGetSymbolAddress((void**)&p_Gt,   g_Gt);
    float* p_cvec; cudaGetSymbolAddress((void**)&p_cvec, g_cvec);
    float* p_obh;  cudaGetSymbolAddress((void**)&p_obh,  g_obh);
    float* p_out;  cudaGetSymbolAddress((void**)&p_out,  g_out);

    // 1. context = concat(x, y)
    pack_ctx<<<eltGrid((long)CTX * BB * DIM_), 256>>>(x, y);

    // 2. q_lin = inp @ Wq^T + bq   [8192, 512]
    gemm_t<128,128><<<dim3(cdiv(INNER_, 128), cdiv(BB * NN_, 128), 1), 256>>>(
        inp, DIM_, 0, Wq, DIM_, 0, bq, nullptr, 0, nullptr, 0, 0,
        p_qlin, INNER_, 0, BB * NN_, INNER_, DIM_, 1.0f);

    // 3. k_ctx = context @ Wkv[0:512]^T + bkv[0:512]   [16384, 512]  (v half dead)
    gemm_t<128,128><<<dim3(cdiv(INNER_, 128), cdiv(BB * CTX, 128), 1), 256>>>(
        p_ctx, DIM_, 0, Wkv, DIM_, 0, bkv, nullptr, 0, nullptr, 0, 0,
        p_kctx, INNER_, 0, BB * CTX, INNER_, DIM_, 1.0f);

    // 4. skv = inp @ Wkv^T + bkv   [8192, 1024]
    gemm_t<128,128><<<dim3(cdiv(2 * INNER_, 128), cdiv(BB * NN_, 128), 1), 256>>>(
        inp, DIM_, 0, Wkv, DIM_, 0, bkv, nullptr, 0, nullptr, 0, 0,
        p_skv, 2 * INNER_, 0, BB * NN_, 2 * INNER_, DIM_, 1.0f);

    // 5. head-split packs (+ memory tokens) and Wf transpose
    pack_Q  <<<eltGrid((long)BB * HH * NN_ * DD), 256>>>();
    pack_K  <<<eltGrid((long)BB * HH * LK * DD), 256>>>(m_k);
    pack_Sk <<<eltGrid((long)BB * HH * LS * DD), 256>>>(Sm_k);
    pack_SvT<<<eltGrid((long)BB * HH * DD * LS), 256>>>(Sm_v);
    transpose_Wf<<<eltGrid((long)LK * LS), 256>>>(Wf);
    calc_cvec<<<cdiv(ZZ * DD * 32, 256), 256>>>(bf);

    // 6. cross scores: P[z] = SCALE * Q[z] @ K[z]^T    [64 x 1024 x 2051]
    gemm_t<128,128><<<dim3(cdiv(LK, 128), cdiv(NN_, 128), ZZ), 256>>>(
        p_Q, DD, (long)NN_ * DD, p_K, DD, (long)LK * DD,
        nullptr, nullptr, 0, nullptr, 0, 0,
        p_P, LK, (long)NN_ * LK, NN_, LK, DD, SCALE_);

    //    self scores: S2[z] = SCALE * Q[z] @ Sk[z]^T   [64 x 1024 x 1027]
    gemm_t<128,128><<<dim3(cdiv(LS, 128), cdiv(NN_, 128), ZZ), 256>>>(
        p_Q, DD, (long)NN_ * DD, p_Sk, DD, (long)LS * DD,
        nullptr, nullptr, 0, nullptr, 0, 0,
        p_S2, LS, (long)NN_ * LS, NN_, LS, DD, SCALE_);

    // 7. softmax
    softmax_rows<<<ZZ * NN_, 256>>>(p_P, LK);
    softmax_rows<<<ZZ * NN_, 256>>>(p_S2, LS);

    // 8a. Gt[z][d,k] = sum_o Sv[o,d]*Wf[o,k]   [64 x (64 x 2051), K=1027]
    //     M=64 exact fit with BM=64 tile (no padding waste)
    gemm_t<64,128><<<dim3(cdiv(LK, 128), 1, ZZ), 256>>>(
        p_SvT, LS, (long)DD * LS, p_WfT, LS, 0,
        nullptr, nullptr, 0, nullptr, 0, 0,
        p_Gt, LK, (long)DD * LK, DD, LK, LS, 1.0f);

    // 8b. obh[z] = S2[z] @ Sv[z]   [64 x 1024 x 64, K=1027]  N=64 exact fit
    gemm_t<128,64><<<dim3(1, cdiv(NN_, 128), ZZ), 256>>>(
        p_S2, LS, (long)NN_ * LS, p_SvT, LS, (long)DD * LS,
        nullptr, nullptr, 0, nullptr, 0, 0,
        p_obh, DD, (long)NN_ * DD, NN_, DD, LS, 1.0f);

    // 8c. obh[z] += P[z] @ Gt[z]^T + cvec[z]   [64 x 1024 x 64, K=2051]
    gemm_t<128,64><<<dim3(1, cdiv(NN_, 128), ZZ), 256>>>(
        p_P, LK, (long)NN_ * LK, p_Gt, LK, (long)DD * LK,
        nullptr, p_cvec, DD, p_obh, DD, (long)NN_ * DD,
        p_obh, DD, (long)NN_ * DD, NN_, DD, LK, 1.0f);

    // 9. merge heads
    pack_out<<<eltGrid((long)BB * NN_ * INNER_), 256>>>();

    // 10. final = out @ Wo^T + bo   [8192, 512]
    gemm_t<128,128><<<dim3(cdiv(DIM_, 128), cdiv(BB * NN_, 128), 1), 256>>>(
        p_out, INNER_, 0, Wo, INNER_, 0, bo, nullptr, 0, nullptr, 0, 0,
        out, DIM_, 0, BB * NN_, DIM_, INNER_, 1.0f);
}

// round 9
// speedup vs baseline: 8.3661x; 1.0839x over previous
#include <cuda_runtime.h>
#include <math.h>

// ---------------- problem constants ----------------
#define BB      8
#define NN_     1024
#define DIM_    512
#define HH      8
#define DD      64
#define INNER_  512
#define MTOK    3
#define CTX     2048            // 2*N
#define LK      2051            // 2N + M
#define LS      1027            // N + M
#define LKP     2052            // LK padded to mult of 4 (pad entries ZERO)
#define LSP     1028            // LS padded to mult of 4 (pad entries ZERO)
#define SCALE_  0.125f          // 64^-0.5
#define SQRT_D  8.0f
#define SQRT_M  1.7320508075688772f
#define ZZ      (BB * HH)       // 64

// ---------------- scratch (device globals; no allocation allowed) ----------------
__device__ float g_ctx  [CTX * BB * DIM_];
__device__ float g_kctx [CTX * BB * INNER_];
__device__ float g_skv  [BB * NN_ * 2 * INNER_];
__device__ float g_qlin [BB * NN_ * INNER_];
__device__ float g_Q    [ZZ * NN_ * DD];
__device__ float g_K    [ZZ * LKP * DD];            // rows LK..LKP-1 are zero
__device__ float g_Sk   [ZZ * LSP * DD];            // rows LS..LSP-1 are zero
__device__ float g_SvT  [ZZ * DD * LSP];            // cols LS..LSP-1 are zero
__device__ float g_P    [(size_t)ZZ * NN_ * LKP];   // pad col stays 0
__device__ float g_S2   [(size_t)ZZ * NN_ * LSP];   // pad col stays 0
__device__ float g_WfT  [LKP * LSP];                // pad row/col zero
__device__ float g_Gt   [ZZ * DD * LKP];
__device__ float g_cvec [ZZ * DD];
__device__ float g_obh  [ZZ * NN_ * DD];
__device__ float g_out  [BB * NN_ * INNER_];

// ---------------- templated NT SGEMM: C = alpha*(A @ W^T) + bias + bias2_z + add ----
// A: [M,K] row-major (lda), W: [N,K] row-major (ldw), C: [M,N] (ldc)
// REQUIREMENTS (guaranteed by all call sites): lda%4==0, ldw%4==0, K%4==0,
// A/W 16B-aligned. Guards zero-fill rows >= M / >= N and k >= K.
// Tile BMt x BNt x 16, 256 threads, double-buffered smem, float4 global loads.
// In-place C == addm is safe (each element read once by its own writer thread).
#define BK 16

template<int BMt, int BNt>
__global__ __launch_bounds__(256, 2)
void gemm_t(const float* __restrict__ A, int lda, long sA,
            const float* __restrict__ W, int ldw, long sW,
            const float* __restrict__ bias,
            const float* __restrict__ bias2, long sB2,
            const float* __restrict__ addm, int ldadd, long sAdd,
            float* __restrict__ C, int ldc, long sC,
            int M, int N, int K, float alpha)
{
    constexpr int RM  = BMt / 16;          // rows per thread
    constexpr int RN  = BNt / 16;          // cols per thread
    constexpr int QPR = BK / 4;            // quad-loads per smem row (4)
    constexpr int RPP = 256 / QPR;         // rows covered per pass (64)
    constexpr int PA  = BMt / RPP;         // passes for A (1 or 2)
    constexpr int PB  = BNt / RPP;         // passes for B (1 or 2)

    __shared__ float As[2][BK][BMt];
    __shared__ float Bs[2][BK][BNt];

    const long bz = blockIdx.z;
    const float* Ab   = A + bz * sA;
    const float* Wb   = W + bz * sW;
    const float* Addb = addm ? (addm + bz * sAdd) : nullptr;
    const float* B2b  = bias2 ? (bias2 + bz * sB2) : nullptr;
    float* Cb = C + bz * sC;

    const int row0 = blockIdx.y * BMt;
    const int col0 = blockIdx.x * BNt;
    const int tid  = threadIdx.x;
    const int tx   = tid & 15;
    const int ty   = tid >> 4;

    const int lq = (tid % QPR) * 4;        // k-offset of this thread's quad
    const int lr = tid / QPR;              // base row (0..63)

    float acc[RM][RN] = {};
    float4 pa[PA], pb[PB];

    const int nk = (K + BK - 1) / BK;

    // ---- fetch tile 0 ----
    #pragma unroll
    for (int p = 0; p < PA; p++) {
        int gr = row0 + lr + p * RPP, gk = lq;
        pa[p] = (gr < M && gk < K)
              ? *reinterpret_cast<const float4*>(&Ab[(long)gr * lda + gk])
              : make_float4(0.f, 0.f, 0.f, 0.f);
    }
    #pragma unroll
    for (int p = 0; p < PB; p++) {
        int gn = col0 + lr + p * RPP, gk = lq;
        pb[p] = (gn < N && gk < K)
              ? *reinterpret_cast<const float4*>(&Wb[(long)gn * ldw + gk])
              : make_float4(0.f, 0.f, 0.f, 0.f);
    }
    #pragma unroll
    for (int p = 0; p < PA; p++) {
        As[0][lq + 0][lr + p * RPP] = pa[p].x;
        As[0][lq + 1][lr + p * RPP] = pa[p].y;
        As[0][lq + 2][lr + p * RPP] = pa[p].z;
        As[0][lq + 3][lr + p * RPP] = pa[p].w;
    }
    #pragma unroll
    for (int p = 0; p < PB; p++) {
        Bs[0][lq + 0][lr + p * RPP] = pb[p].x;
        Bs[0][lq + 1][lr + p * RPP] = pb[p].y;
        Bs[0][lq + 2][lr + p * RPP] = pb[p].z;
        Bs[0][lq + 3][lr + p * RPP] = pb[p].w;
    }
    __syncthreads();

    int buf = 0;
    for (int t = 0; t < nk; t++) {
        // prefetch next tile (overlaps with compute)
        if (t + 1 < nk) {
            const int k0 = (t + 1) * BK;
            #pragma unroll
            for (int p = 0; p < PA; p++) {
                int gr = row0 + lr + p * RPP, gk = k0 + lq;
                pa[p] = (gr < M && gk < K)
                      ? *reinterpret_cast<const float4*>(&Ab[(long)gr * lda + gk])
                      : make_float4(0.f, 0.f, 0.f, 0.f);
            }
            #pragma unroll
            for (int p = 0; p < PB; p++) {
                int gn = col0 + lr + p * RPP, gk = k0 + lq;
                pb[p] = (gn < N && gk < K)
                      ? *reinterpret_cast<const float4*>(&Wb[(long)gn * ldw + gk])
                      : make_float4(0.f, 0.f, 0.f, 0.f);
            }
        }

        #pragma unroll
        for (int kk = 0; kk < BK; kk++) {
            float a[RM], b[RN];
            #pragma unroll
            for (int g = 0; g < RM / 4; g++) {
                float4 v = *reinterpret_cast<const float4*>(&As[buf][kk][g * 64 + ty * 4]);
                a[g * 4 + 0] = v.x; a[g * 4 + 1] = v.y;
                a[g * 4 + 2] = v.z; a[g * 4 + 3] = v.w;
            }
            #pragma unroll
            for (int g = 0; g < RN / 4; g++) {
                float4 v = *reinterpret_cast<const float4*>(&Bs[buf][kk][g * 64 + tx * 4]);
                b[g * 4 + 0] = v.x; b[g * 4 + 1] = v.y;
                b[g * 4 + 2] = v.z; b[g * 4 + 3] = v.w;
            }
            #pragma unroll
            for (int i = 0; i < RM; i++)
                #pragma unroll
                for (int j = 0; j < RN; j++)
                    acc[i][j] = fmaf(a[i], b[j], acc[i][j]);
        }

        if (t + 1 < nk) {
            #pragma unroll
            for (int p = 0; p < PA; p++) {
                As[buf ^ 1][lq + 0][lr + p * RPP] = pa[p].x;
                As[buf ^ 1][lq + 1][lr + p * RPP] = pa[p].y;
                As[buf ^ 1][lq + 2][lr + p * RPP] = pa[p].z;
                As[buf ^ 1][lq + 3][lr + p * RPP] = pa[p].w;
            }
            #pragma unroll
            for (int p = 0; p < PB; p++) {
                Bs[buf ^ 1][lq + 0][lr + p * RPP] = pb[p].x;
                Bs[buf ^ 1][lq + 1][lr + p * RPP] = pb[p].y;
                Bs[buf ^ 1][lq + 2][lr + p * RPP] = pb[p].z;
                Bs[buf ^ 1][lq + 3][lr + p * RPP] = pb[p].w;
            }
            __syncthreads();
            buf ^= 1;
        }
    }

    // ---- fused epilogue ----
    #pragma unroll
    for (int i = 0; i < RM; i++) {
        int r = row0 + (i / 4) * 64 + ty * 4 + (i % 4);
        if (r >= M) continue;
        #pragma unroll
        for (int j = 0; j < RN; j++) {
            int c = col0 + (j / 4) * 64 + tx * 4 + (j % 4);
            if (c >= N) continue;
            float v = alpha * acc[i][j];
            if (bias) v += bias[c];
            if (B2b)  v += B2b[c];
            if (Addb) v += Addb[(long)r * ldadd + c];
            Cb[(long)r * ldc + c] = v;
        }
    }
}

// ---------------- row softmax (one block per row, strided rows) ----------------
__global__ __launch_bounds__(256)
void softmax_rows(float* __restrict__ data, int cols, int ld)
{
    const long row = blockIdx.x;
    float* p = data + row * (long)ld;
    const int tid = threadIdx.x;
    __shared__ float sh[256];

    float mx = -3.0e38f;
    for (int c = tid; c < cols; c += 256) mx = fmaxf(mx, p[c]);
    sh[tid] = mx; __syncthreads();
    for (int s = 128; s > 0; s >>= 1) {
        if (tid < s) sh[tid] = fmaxf(sh[tid], sh[tid + s]);
        __syncthreads();
    }
    mx = sh[0]; __syncthreads();

    float sum = 0.0f;
    for (int c = tid; c < cols; c += 256) {
        float e = __expf(p[c] - mx);
        p[c] = e;
        sum += e;
    }
    sh[tid] = sum; __syncthreads();
    for (int s = 128; s > 0; s >>= 1) {
        if (tid < s) sh[tid] += sh[tid + s];
        __syncthreads();
    }
    float inv = 1.0f / sh[0];
    for (int c = tid; c < cols; c += 256) p[c] *= inv;
}

// ---------------- pack kernels ----------------
__global__ void pack_ctx(const float* __restrict__ x, const float* __restrict__ y)
{
    long idx = (long)blockIdx.x * blockDim.x + threadIdx.x;
    const long total = (long)CTX * BB * DIM_;
    if (idx >= total) return;
    long b = idx / ((long)CTX * DIM_);
    long rem = idx - b * (long)CTX * DIM_;
    long j = rem / DIM_;
    long c = rem - j * DIM_;
    g_ctx[idx] = (j < NN_) ? x[(b * NN_ + j) * DIM_ + c]
                           : y[(b * NN_ + (j - NN_)) * DIM_ + c];
}

__global__ void pack_Q()
{
    long idx = (long)blockIdx.x * blockDim.x + threadIdx.x;
    const long total = (long)ZZ * NN_ * DD;
    if (idx >= total) return;
    long z = idx / ((long)NN_ * DD);
    long rem = idx - z * (long)NN_ * DD;
    long n = rem / DD, d = rem - n * DD;
    long b = z >> 3, h = z & 7;
    g_Q[idx] = g_qlin[(b * NN_ + n) * INNER_ + h * DD + d];
}

__global__ void pack_K(const float* __restrict__ m_k)
{
    long idx = (long)blockIdx.x * blockDim.x + threadIdx.x;
    const long total = (long)ZZ * LKP * DD;
    if (idx >= total) return;
    long z = idx / ((long)LKP * DD);
    long rem = idx - z * (long)LKP * DD;
    long j = rem / DD, d = rem - j * DD;
    long b = z >> 3, h = z & 7;
    float v;
    if (j < CTX)      v = g_kctx[(b * CTX + j) * INNER_ + h * DD + d];
    else if (j < LK)  v = SQRT_D * m_k[h * (MTOK * DD) + (j - CTX) * DD + d];
    else              v = 0.0f;       // pad row -> P pad col = 0
    g_K[idx] = v;
}

__global__ void pack_Sk(const float* __restrict__ Sm_k)
{
    long idx = (long)blockIdx.x * blockDim.x + threadIdx.x;
    const long total = (long)ZZ * LSP * DD;
    if (idx >= total) return;
    long z = idx / ((long)LSP * DD);
    long rem = idx - z * (long)LSP * DD;
    long j = rem / DD, d = rem - j * DD;
    long b = z >> 3, h = z & 7;
    float v;
    if (j < NN_)      v = g_skv[(b * NN_ + j) * (2 * INNER_) + h * DD + d];
    else if (j < LS)  v = SQRT_D * Sm_k[h * (MTOK * DD) + (j - NN_) * DD + d];
    else              v = 0.0f;       // pad row -> S2 pad col = 0
    g_Sk[idx] = v;
}

__global__ void pack_SvT(const float* __restrict__ Sm_v)
{
    long idx = (long)blockIdx.x * blockDim.x + threadIdx.x;
    const long total = (long)ZZ * DD * LSP;
    if (idx >= total) return;
    long z = idx / ((long)DD * LSP);
    long rem = idx - z * (long)DD * LSP;
    long d = rem / LSP, j = rem - d * LSP;
    long b = z >> 3, h = z & 7;
    float v;
    if (j < NN_)      v = g_skv[(b * NN_ + j) * (2 * INNER_) + INNER_ + h * DD + d];
    else if (j < LS)  v = SQRT_M * Sm_v[h * (MTOK * DD) + (j - NN_) * DD + d];
    else              v = 0.0f;       // pad col zero
    g_SvT[idx] = v;
}

// WfT[k, o] = Wf[o, k], zero-padded to [LKP, LSP]
__global__ void transpose_Wf(const float* __restrict__ Wf)
{
    long idx = (long)blockIdx.x * blockDim.x + threadIdx.x;
    const long total = (long)LKP * LSP;
    if (idx >= total) return;
    long k = idx / LSP, o = idx - k * LSP;
    g_WfT[idx] = (k < LK && o < LS) ? Wf[o * (long)LK + k] : 0.0f;
}

// cvec[z, d] = sum_o bf[o] * SvT[z, d, o]   (one warp per (z,d))
__global__ void calc_cvec(const float* __restrict__ bf)
{
    int warp = (blockIdx.x * blockDim.x + threadIdx.x) >> 5;
    int lane = threadIdx.x & 31;
    if (warp >= ZZ * DD) return;
    const float* sv = g_SvT + (long)warp * LSP;
    float s = 0.0f;
    for (int o = lane; o < LS; o += 32) s += bf[o] * sv[o];
    #pragma unroll
    for (int sft = 16; sft > 0; sft >>= 1)
        s += __shfl_xor_sync(0xFFFFFFFF, s, sft);
    if (lane == 0) g_cvec[warp] = s;
}

__global__ void pack_out()
{
    long idx = (long)blockIdx.x * blockDim.x + threadIdx.x;
    const long total = (long)BB * NN_ * INNER_;
    if (idx >= total) return;
    long b = idx / ((long)NN_ * INNER_);
    long rem = idx - b * (long)NN_ * INNER_;
    long n = rem / INNER_;
    long c = rem - n * INNER_;
    long h = c / DD, d = c - h * DD;
    g_out[idx] = g_obh[((b * HH + h) * NN_ + n) * DD + d];
}

// ---------------- launch ----------------
static inline dim3 eltGrid(long n) { return dim3((unsigned)((n + 255) / 256)); }
static inline unsigned cdiv(int a, int b) { return (unsigned)((a + b - 1) / b); }

extern "C" void kernel_launch(void* const* d_in, const int* in_sizes, int n_in,
                              void* d_out, int out_size)
{
    const float* inp  = (const float*)d_in[0];
    const float* x    = (const float*)d_in[1];
    const float* y    = (const float*)d_in[2];
    const float* Wq   = (const float*)d_in[3];
    const float* bq   = (const float*)d_in[4];
    const float* Wkv  = (const float*)d_in[5];
    const float* bkv  = (const float*)d_in[6];
    const float* Wf   = (const float*)d_in[7];
    const float* bf   = (const float*)d_in[8];
    const float* Wo   = (const float*)d_in[9];
    const float* bo   = (const float*)d_in[10];
    const float* m_k  = (const float*)d_in[11];
    // d_in[12] = m_v : unused (cross-attention v never feeds the output)
    const float* Sm_k = (const float*)d_in[13];
    const float* Sm_v = (const float*)d_in[14];
    float* out = (float*)d_out;

    float* p_ctx;  cudaGetSymbolAddress((void**)&p_ctx,  g_ctx);
    float* p_kctx; cudaGetSymbolAddress((void**)&p_kctx, g_kctx);
    float* p_skv;  cudaGetSymbolAddress((void**)&p_skv,  g_skv);
    float* p_qlin; cudaGetSymbolAddress((void**)&p_qlin, g_qlin);
    float* p_Q;    cudaGetSymbolAddress((void**)&p_Q,    g_Q);
    float* p_K;    cudaGetSymbolAddress((void**)&p_K,    g_K);
    float* p_Sk;   cudaGetSymbolAddress((void**)&p_Sk,   g_Sk);
    float* p_SvT;  cudaGetSymbolAddress((void**)&p_SvT,  g_SvT);
    float* p_P;    cudaGetSymbolAddress((void**)&p_P,    g_P);
    float* p_S2;   cudaGetSymbolAddress((void**)&p_S2,   g_S2);
    float* p_WfT;  cudaGetSymbolAddress((void**)&p_WfT,  g_WfT);
    float* p_Gt;   cudaGetSymbolAddress((void**)&p_Gt,   g_Gt);
    float* p_cvec; cudaGetSymbolAddress((void**)&p_cvec, g_cvec);
    float* p_obh;  cudaGetSymbolAddress((void**)&p_obh,  g_obh);
    float* p_out;  cudaGetSymbolAddress((void**)&p_out,  g_out);

    // 1. context = concat(x, y)
    pack_ctx<<<eltGrid((long)CTX * BB * DIM_), 256>>>(x, y);

    // 2. q_lin = inp @ Wq^T + bq   [8192, 512] K=512
    gemm_t<128,128><<<dim3(cdiv(INNER_, 128), cdiv(BB * NN_, 128), 1), 256>>>(
        inp, DIM_, 0, Wq, DIM_, 0, bq, nullptr, 0, nullptr, 0, 0,
        p_qlin, INNER_, 0, BB * NN_, INNER_, DIM_, 1.0f);

    // 3. k_ctx = context @ Wkv[0:512]^T + bkv[0:512]   [16384, 512]
    gemm_t<128,128><<<dim3(cdiv(INNER_, 128), cdiv(BB * CTX, 128), 1), 256>>>(
        p_ctx, DIM_, 0, Wkv, DIM_, 0, bkv, nullptr, 0, nullptr, 0, 0,
        p_kctx, INNER_, 0, BB * CTX, INNER_, DIM_, 1.0f);

    // 4. skv = inp @ Wkv^T + bkv   [8192, 1024]
    gemm_t<128,128><<<dim3(cdiv(2 * INNER_, 128), cdiv(BB * NN_, 128), 1), 256>>>(
        inp, DIM_, 0, Wkv, DIM_, 0, bkv, nullptr, 0, nullptr, 0, 0,
        p_skv, 2 * INNER_, 0, BB * NN_, 2 * INNER_, DIM_, 1.0f);

    // 5. head-split packs (+ memory tokens, + zero pads) and Wf transpose
    pack_Q  <<<eltGrid((long)ZZ * NN_ * DD), 256>>>();
    pack_K  <<<eltGrid((long)ZZ * LKP * DD), 256>>>(m_k);
    pack_Sk <<<eltGrid((long)ZZ * LSP * DD), 256>>>(Sm_k);
    pack_SvT<<<eltGrid((long)ZZ * DD * LSP), 256>>>(Sm_v);
    transpose_Wf<<<eltGrid((long)LKP * LSP), 256>>>(Wf);
    calc_cvec<<<cdiv(ZZ * DD * 32, 256), 256>>>(bf);

    // 6. cross scores: P[z] = SCALE * Q[z] @ K[z]^T   [64 x 1024 x 2052] K=64
    //    (N includes zero pad row -> P pad col = 0)
    gemm_t<128,128><<<dim3(cdiv(LKP, 128), cdiv(NN_, 128), ZZ), 256>>>(
        p_Q, DD, (long)NN_ * DD, p_K, DD, (long)LKP * DD,
        nullptr, nullptr, 0, nullptr, 0, 0,
        p_P, LKP, (long)NN_ * LKP, NN_, LKP, DD, SCALE_);

    //    self scores: S2[z] = SCALE * Q[z] @ Sk[z]^T   [64 x 1024 x 1028] K=64
    gemm_t<128,128><<<dim3(cdiv(LSP, 128), cdiv(NN_, 128), ZZ), 256>>>(
        p_Q, DD, (long)NN_ * DD, p_Sk, DD, (long)LSP * DD,
        nullptr, nullptr, 0, nullptr, 0, 0,
        p_S2, LSP, (long)NN_ * LSP, NN_, LSP, DD, SCALE_);

    // 7. softmax over real cols only (pad cols stay 0)
    softmax_rows<<<ZZ * NN_, 256>>>(p_P, LK, LKP);
    softmax_rows<<<ZZ * NN_, 256>>>(p_S2, LS, LSP);

    // 8a. Gt[z][d,k] = sum_o Sv[o,d]*Wf[o,k]   [64 x (64 x 2052), K=1028]
    gemm_t<64,128><<<dim3(cdiv(LKP, 128), 1, ZZ), 256>>>(
        p_SvT, LSP, (long)DD * LSP, p_WfT, LSP, 0,
        nullptr, nullptr, 0, nullptr, 0, 0,
        p_Gt, LKP, (long)DD * LKP, DD, LKP, LSP, 1.0f);

    // 8b. obh[z] = S2[z] @ Sv[z]   [64 x 1024 x 64, K=1028]
    gemm_t<128,64><<<dim3(1, cdiv(NN_, 128), ZZ), 256>>>(
        p_S2, LSP, (long)NN_ * LSP, p_SvT, LSP, (long)DD * LSP,
        nullptr, nullptr, 0, nullptr, 0, 0,
        p_obh, DD, (long)NN_ * DD, NN_, DD, LSP, 1.0f);

    // 8c. obh[z] += P[z] @ Gt[z]^T + cvec[z]   [64 x 1024 x 64, K=2052]
    gemm_t<128,64><<<dim3(1, cdiv(NN_, 128), ZZ), 256>>>(
        p_P, LKP, (long)NN_ * LKP, p_Gt, LKP, (long)DD * LKP,
        nullptr, p_cvec, DD, p_obh, DD, (long)NN_ * DD,
        p_obh, DD, (long)NN_ * DD, NN_, DD, LKP, 1.0f);

    // 9. merge heads
    pack_out<<<eltGrid((long)BB * NN_ * INNER_), 256>>>();

    // 10. final = out @ Wo^T + bo   [8192, 512] K=512
    gemm_t<128,128><<<dim3(cdiv(DIM_, 128), cdiv(BB * NN_, 128), 1), 256>>>(
        p_out, INNER_, 0, Wo, INNER_, 0, bo, nullptr, 0, nullptr, 0, 0,
        out, DIM_, 0, BB * NN_, DIM_, INNER_, 1.0f);
}

// round 11
// speedup vs baseline: 12.0691x; 1.4426x over previous
#include <cuda_runtime.h>
#include <cuda_bf16.h>
#include <math.h>
#include <stdint.h>

// ---------------- problem constants ----------------
#define BB      8
#define NN_     1024
#define DIM_    512
#define HH      8
#define DD      64
#define INNER_  512
#define MTOK    3
#define CTX     2048            // 2*N
#define LK      2051            // 2N + M
#define LS      1027            // N + M
#define LKP     2064            // LK padded to mult of 16 (pads ZERO)
#define LSP     1040            // LS padded to mult of 16 (pads ZERO)
#define SCALE_  0.125f
#define SQRT_D  8.0f
#define SQRT_M  1.7320508075688772f
#define ZZ      (BB * HH)       // 64

typedef __nv_bfloat16 bf16;

// ---------------- scratch (device globals; no allocation allowed) ----------------
// split-bf16 pairs (hi, lo): x ~= hi + lo, error ~2^-16 relative
__device__ bf16 g_inp_h [BB * NN_ * DIM_],        g_inp_l [BB * NN_ * DIM_];
__device__ bf16 g_ctx_h [CTX * BB * DIM_],        g_ctx_l [CTX * BB * DIM_];
__device__ bf16 g_Wq_h  [INNER_ * DIM_],          g_Wq_l  [INNER_ * DIM_];
__device__ bf16 g_Wkv_h [2 * INNER_ * DIM_],      g_Wkv_l [2 * INNER_ * DIM_];
__device__ bf16 g_Wo_h  [DIM_ * INNER_],          g_Wo_l  [DIM_ * INNER_];
__device__ bf16 g_qlin_h[BB * NN_ * INNER_],      g_qlin_l[BB * NN_ * INNER_];
__device__ bf16 g_kctx_h[CTX * BB * INNER_],      g_kctx_l[CTX * BB * INNER_];
__device__ bf16 g_skv_h [BB * NN_ * 2 * INNER_],  g_skv_l [BB * NN_ * 2 * INNER_];
__device__ bf16 g_Q_h   [ZZ * NN_ * DD],          g_Q_l   [ZZ * NN_ * DD];
__device__ bf16 g_K_h   [ZZ * LKP * DD],          g_K_l   [ZZ * LKP * DD];
__device__ bf16 g_Sk_h  [ZZ * LSP * DD],          g_Sk_l  [ZZ * LSP * DD];
__device__ bf16 g_SvT_h [ZZ * DD * LSP],          g_SvT_l [ZZ * DD * LSP];
__device__ bf16 g_WfT_h [LKP * LSP],              g_WfT_l [LKP * LSP];
__device__ bf16 g_Ph    [(size_t)ZZ * NN_ * LKP], g_Pl    [(size_t)ZZ * NN_ * LKP];
__device__ bf16 g_S2h   [(size_t)ZZ * NN_ * LSP], g_S2l   [(size_t)ZZ * NN_ * LSP];
__device__ bf16 g_Gt_h  [ZZ * DD * LKP],          g_Gt_l  [ZZ * DD * LKP];
__device__ bf16 g_outp_h[BB * NN_ * INNER_],      g_outp_l[BB * NN_ * INNER_];
// fp32 scratch
__device__ float g_P    [(size_t)ZZ * NN_ * LKP];  // raw logits (pads never read)
__device__ float g_S2   [(size_t)ZZ * NN_ * LSP];
__device__ float g_cvec [ZZ * DD];
__device__ float g_obh  [ZZ * NN_ * DD];

// ---------------- helpers ----------------
__device__ __forceinline__ void wsplit(float v, bf16* hi, bf16* lo, long idx)
{
    bf16 h = __float2bfloat16(v);
    hi[idx] = h;
    lo[idx] = __float2bfloat16(v - __bfloat162float(h));
}

__device__ __forceinline__ void ldsm4(uint32_t* r, uint32_t a)
{
    asm volatile("ldmatrix.sync.aligned.m8n8.x4.shared.b16 {%0,%1,%2,%3}, [%4];"
        : "=r"(r[0]), "=r"(r[1]), "=r"(r[2]), "=r"(r[3]) : "r"(a));
}
__device__ __forceinline__ void ldsm2(uint32_t* r, uint32_t a)
{
    asm volatile("ldmatrix.sync.aligned.m8n8.x2.shared.b16 {%0,%1}, [%2];"
        : "=r"(r[0]), "=r"(r[1]) : "r"(a));
}
__device__ __forceinline__ void mma16816(float* d, const uint32_t* a, const uint32_t* b)
{
    asm volatile("mma.sync.aligned.m16n8k16.row.col.f32.bf16.bf16.f32 "
        "{%0,%1,%2,%3},{%4,%5,%6,%7},{%8,%9},{%0,%1,%2,%3};"
        : "+f"(d[0]), "+f"(d[1]), "+f"(d[2]), "+f"(d[3])
        : "r"(a[0]), "r"(a[1]), "r"(a[2]), "r"(a[3]), "r"(b[0]), "r"(b[1]));
}

// ---------------- split-bf16 tensor-core NT GEMM --------------------------------
// C = alpha * (A @ W^T) + bias + bias2_z + add, where A ~= Ahi+Alo, W ~= Whi+Wlo.
// A: [M,K] rows (lda), W: [N,K] rows (ldw); lda/ldw mult of 8; K mult of 16.
// Outputs: fp32 C (optional) and/or split bf16 Chi/Clo (optional), same ldc.
// In-place C == addm safe (read-before-write by owning thread).
template<int BM, int BN>
__global__ __launch_bounds__(256)
void gemm_bf(const bf16* __restrict__ Ahi, const bf16* __restrict__ Alo, int lda, long sA,
             const bf16* __restrict__ Whi, const bf16* __restrict__ Wlo, int ldw, long sW,
             const float* __restrict__ bias,
             const float* __restrict__ bias2, long sB2,
             const float* __restrict__ addm, int ldadd, long sAdd,
             float* __restrict__ C, bf16* __restrict__ Chi, bf16* __restrict__ Clo,
             int ldc, long sC,
             int M, int N, int K, float alpha)
{
    constexpr int WARPS_M = (BM >= 128) ? 2 : 1;
    constexpr int WARPS_N = 8 / WARPS_M;
    constexpr int WM = BM / WARPS_M;       // 64
    constexpr int WN = BN / WARPS_N;       // 32 or 16
    constexpr int MI = WM / 16;            // 4
    constexpr int NJ = WN / 8;             // 4 or 2
    constexpr int R  = BM + BN;            // smem rows (A then B)
    constexpr int LDS = 40;                // elems/row: 16 hi | 16 lo | 8 pad

    __shared__ __align__(16) bf16 sm[2][R][LDS];

    const long bz = blockIdx.z;
    const bf16* Ah_b = Ahi + bz * sA;
    const bf16* Al_b = Alo + bz * sA;
    const bf16* Wh_b = Whi + bz * sW;
    const bf16* Wl_b = Wlo + bz * sW;
    const float* Addb = addm ? (addm + bz * sAdd) : nullptr;
    const float* B2b  = bias2 ? (bias2 + bz * sB2) : nullptr;
    float* Cb   = C   ? (C   + bz * sC) : nullptr;
    bf16*  Chib = Chi ? (Chi + bz * sC) : nullptr;
    bf16*  Clob = Clo ? (Clo + bz * sC) : nullptr;

    const int row0 = blockIdx.y * BM;
    const int col0 = blockIdx.x * BN;
    const int tid  = threadIdx.x;
    const int lane = tid & 31;
    const int warp = tid >> 5;
    const int wm   = warp % WARPS_M;
    const int wn   = warp / WARPS_M;

    // ---- global loader setup (thread tid owns smem row tid) ----
    bool ldValid;
    long rowOff = 0;
    const bf16 *srcH = Ah_b, *srcL = Al_b;
    if (tid < BM) {
        int gr = row0 + tid;
        ldValid = gr < M;
        rowOff = (long)gr * lda;
    } else {
        int rb = tid - BM;
        int gn = col0 + rb;
        ldValid = (rb < BN) && (gn < N);
        rowOff = (long)gn * ldw;
        srcH = Wh_b; srcL = Wl_b;
    }
    uint4 u[4];

    // ldmatrix base offsets (bytes), natural chunk positions (conflict-free loads)
    const uint32_t sbase = (uint32_t)__cvta_generic_to_shared(&sm[0][0][0]);
    uint32_t aoff[MI], boff[NJ];
    #pragma unroll
    for (int i = 0; i < MI; i++)
        aoff[i] = (uint32_t)(((wm * WM + i * 16 + (lane & 15)) * LDS + ((lane >> 4) * 8)) * 2);
    #pragma unroll
    for (int j = 0; j < NJ; j++)
        boff[j] = (uint32_t)(((BM + wn * WN + j * 8 + (lane & 7)) * LDS + (((lane >> 3) & 1) * 8)) * 2);

    float acc[MI][NJ][4] = {};

    const int nk = K / 16;

    // rotated-chunk gmem->reg load: chunk c=(q+tid)&3; c<2 -> hi bytes, else lo
#define LOADG(k0) do {                                                          \
        _Pragma("unroll")                                                       \
        for (int q = 0; q < 4; q++) {                                           \
            int c = (q + tid) & 3;                                              \
            const bf16* sp = (c < 2) ? srcH : srcL;                             \
            u[q] = ldValid                                                      \
                 ? *reinterpret_cast<const uint4*>(sp + rowOff + (k0) + (c & 1) * 8) \
                 : make_uint4(0u, 0u, 0u, 0u);                                  \
        } } while (0)

#define STORES(b) do {                                                          \
        if (tid < R) {                                                          \
            _Pragma("unroll")                                                   \
            for (int q = 0; q < 4; q++) {                                       \
                int c = (q + tid) & 3;                                          \
                *reinterpret_cast<uint4*>(&sm[b][tid][c * 8]) = u[q];           \
            }                                                                   \
        } } while (0)

    LOADG(0);
    STORES(0);
    __syncthreads();

    for (int t = 0; t < nk; t++) {
        const int buf = t & 1;
        if (t + 1 < nk) LOADG((t + 1) * 16);

        const uint32_t bb = sbase + (uint32_t)(buf * (R * LDS * 2));
        uint32_t Ah[MI][4], Al[MI][4], Bh[NJ][2], Bl[NJ][2];
        #pragma unroll
        for (int i = 0; i < MI; i++) {
            ldsm4(Ah[i], bb + aoff[i]);
            ldsm4(Al[i], bb + aoff[i] + 32);   // lo chunk at elem 16 = byte 32
        }
        #pragma unroll
        for (int j = 0; j < NJ; j++) {
            ldsm2(Bh[j], bb + boff[j]);
            ldsm2(Bl[j], bb + boff[j] + 32);
        }
        #pragma unroll
        for (int i = 0; i < MI; i++)
            #pragma unroll
            for (int j = 0; j < NJ; j++) {
                mma16816(acc[i][j], Ah[i], Bh[j]);   // hi*hi
                mma16816(acc[i][j], Ah[i], Bl[j]);   // hi*lo
                mma16816(acc[i][j], Al[i], Bh[j]);   // lo*hi
            }

        if (t + 1 < nk) {
            STORES(buf ^ 1);
            __syncthreads();
        }
    }
#undef LOADG
#undef STORES

    // ---- epilogue ----
    const int rbase = row0 + wm * WM + (lane >> 2);
    const int cbase = col0 + wn * WN + (lane & 3) * 2;
    #pragma unroll
    for (int i = 0; i < MI; i++)
        #pragma unroll
        for (int j = 0; j < NJ; j++)
            #pragma unroll
            for (int e = 0; e < 4; e++) {
                int r = rbase + i * 16 + (e >> 1) * 8;
                int c = cbase + j * 8 + (e & 1);
                if (r < M && c < N) {
                    float v = alpha * acc[i][j][e];
                    if (bias) v += bias[c];
                    if (B2b)  v += B2b[c];
                    if (Addb) v += Addb[(long)r * ldadd + c];
                    long o = (long)r * ldc + c;
                    if (Cb) Cb[o] = v;
                    if (Chib) {
                        bf16 h = __float2bfloat16(v);
                        Chib[o] = h;
                        Clob[o] = __float2bfloat16(v - __bfloat162float(h));
                    }
                }
            }
}

// ---------------- register-resident softmax -> split bf16 ----------------
// One block per row. Reads fp32 src (ld stride), softmax over [0, cols),
// writes split bf16 to dhi/dlo; pads [cols, ld) written as ZERO (required
// by the K-extended downstream MMAs).
__global__ __launch_bounds__(256)
void softmax_split(const float* __restrict__ src,
                   bf16* __restrict__ dhi, bf16* __restrict__ dlo,
                   int cols, int ld)
{
    const long row = blockIdx.x;
    const float* p = src + row * (long)ld;
    bf16* ph = dhi + row * (long)ld;
    bf16* pl = dlo + row * (long)ld;
    const int tid = threadIdx.x;
    __shared__ float sh[256];

    float v[9];
    float mx = -3.0e38f;
    #pragma unroll
    for (int i = 0; i < 9; i++) {
        int c = tid + i * 256;
        if (c < cols) { v[i] = p[c]; mx = fmaxf(mx, v[i]); }
    }
    sh[tid] = mx; __syncthreads();
    for (int s = 128; s > 0; s >>= 1) {
        if (tid < s) sh[tid] = fmaxf(sh[tid], sh[tid + s]);
        __syncthreads();
    }
    mx = sh[0]; __syncthreads();

    float sum = 0.0f;
    #pragma unroll
    for (int i = 0; i < 9; i++) {
        int c = tid + i * 256;
        if (c < cols) { float e = __expf(v[i] - mx); v[i] = e; sum += e; }
    }
    sh[tid] = sum; __syncthreads();
    for (int s = 128; s > 0; s >>= 1) {
        if (tid < s) sh[tid] += sh[tid + s];
        __syncthreads();
    }
    float inv = 1.0f / sh[0];

    #pragma unroll
    for (int i = 0; i < 9; i++) {
        int c = tid + i * 256;
        if (c < cols) {
            float e = v[i] * inv;
            bf16 h = __float2bfloat16(e);
            ph[c] = h;
            pl[c] = __float2bfloat16(e - __bfloat162float(h));
        }
    }
    for (int c = cols + tid; c < ld; c += 256) { ph[c] = __float2bfloat16(0.f); pl[c] = __float2bfloat16(0.f); }
}

// ---------------- conversion / pack kernels ----------------
__global__ void split_arr(const float* __restrict__ src, bf16* __restrict__ hi,
                          bf16* __restrict__ lo, long n)
{
    long i = (long)blockIdx.x * blockDim.x + threadIdx.x;
    if (i < n) wsplit(src[i], hi, lo, i);
}

__global__ void pack_ctx_split(const float* __restrict__ x, const float* __restrict__ y)
{
    long idx = (long)blockIdx.x * blockDim.x + threadIdx.x;
    const long total = (long)CTX * BB * DIM_;
    if (idx >= total) return;
    long b = idx / ((long)CTX * DIM_);
    long rem = idx - b * (long)CTX * DIM_;
    long j = rem / DIM_, c = rem - j * DIM_;
    float v = (j < NN_) ? x[(b * NN_ + j) * DIM_ + c]
                        : y[(b * NN_ + (j - NN_)) * DIM_ + c];
    wsplit(v, g_ctx_h, g_ctx_l, idx);
}

__global__ void pack_Q_split()
{
    long idx = (long)blockIdx.x * blockDim.x + threadIdx.x;
    const long total = (long)ZZ * NN_ * DD;
    if (idx >= total) return;
    long z = idx / ((long)NN_ * DD);
    long rem = idx - z * (long)NN_ * DD;
    long n = rem / DD, d = rem - n * DD;
    long b = z >> 3, h = z & 7;
    long s = (b * NN_ + n) * INNER_ + h * DD + d;
    g_Q_h[idx] = g_qlin_h[s];
    g_Q_l[idx] = g_qlin_l[s];
}

__global__ void pack_K_split(const float* __restrict__ m_k)
{
    long idx = (long)blockIdx.x * blockDim.x + threadIdx.x;
    const long total = (long)ZZ * LKP * DD;
    if (idx >= total) return;
    long z = idx / ((long)LKP * DD);
    long rem = idx - z * (long)LKP * DD;
    long j = rem / DD, d = rem - j * DD;
    long b = z >> 3, h = z & 7;
    if (j < CTX) {
        long s = (b * CTX + j) * INNER_ + h * DD + d;
        g_K_h[idx] = g_kctx_h[s];
        g_K_l[idx] = g_kctx_l[s];
    } else if (j < LK) {
        wsplit(SQRT_D * m_k[h * (MTOK * DD) + (j - CTX) * DD + d], g_K_h, g_K_l, idx);
    } else {
        g_K_h[idx] = __float2bfloat16(0.f);
        g_K_l[idx] = __float2bfloat16(0.f);
    }
}

__global__ void pack_Sk_split(const float* __restrict__ Sm_k)
{
    long idx = (long)blockIdx.x * blockDim.x + threadIdx.x;
    const long total = (long)ZZ * LSP * DD;
    if (idx >= total) return;
    long z = idx / ((long)LSP * DD);
    long rem = idx - z * (long)LSP * DD;
    long j = rem / DD, d = rem - j * DD;
    long b = z >> 3, h = z & 7;
    if (j < NN_) {
        long s = (b * NN_ + j) * (2 * INNER_) + h * DD + d;
        g_Sk_h[idx] = g_skv_h[s];
        g_Sk_l[idx] = g_skv_l[s];
    } else if (j < LS) {
        wsplit(SQRT_D * Sm_k[h * (MTOK * DD) + (j - NN_) * DD + d], g_Sk_h, g_Sk_l, idx);
    } else {
        g_Sk_h[idx] = __float2bfloat16(0.f);
        g_Sk_l[idx] = __float2bfloat16(0.f);
    }
}

__global__ void pack_SvT_split(const float* __restrict__ Sm_v)
{
    long idx = (long)blockIdx.x * blockDim.x + threadIdx.x;
    const long total = (long)ZZ * DD * LSP;
    if (idx >= total) return;
    long z = idx / ((long)DD * LSP);
    long rem = idx - z * (long)DD * LSP;
    long d = rem / LSP, j = rem - d * LSP;
    long b = z >> 3, h = z & 7;
    if (j < NN_) {
        long s = (b * NN_ + j) * (2 * INNER_) + INNER_ + h * DD + d;
        g_SvT_h[idx] = g_skv_h[s];
        g_SvT_l[idx] = g_skv_l[s];
    } else if (j < LS) {
        wsplit(SQRT_M * Sm_v[h * (MTOK * DD) + (j - NN_) * DD + d], g_SvT_h, g_SvT_l, idx);
    } else {
        g_SvT_h[idx] = __float2bfloat16(0.f);
        g_SvT_l[idx] = __float2bfloat16(0.f);
    }
}

// WfT[k, o] = Wf[o, k], split bf16, zero-padded to [LKP, LSP]
__global__ void transpose_WfT(const float* __restrict__ Wf)
{
    long idx = (long)blockIdx.x * blockDim.x + threadIdx.x;
    const long total = (long)LKP * LSP;
    if (idx >= total) return;
    long k = idx / LSP, o = idx - k * LSP;
    float v = (k < LK && o < LS) ? Wf[o * (long)LK + k] : 0.0f;
    wsplit(v, g_WfT_h, g_WfT_l, idx);
}

// cvec[z, d] = sum_o bf[o] * Sv[z, o, d]  (SvT join hi+lo; one warp per (z,d))
__global__ void calc_cvec(const float* __restrict__ bf)
{
    int w = (blockIdx.x * blockDim.x + threadIdx.x) >> 5;
    int lane = threadIdx.x & 31;
    if (w >= ZZ * DD) return;
    const bf16* sh_ = g_SvT_h + (long)w * LSP;
    const bf16* sl_ = g_SvT_l + (long)w * LSP;
    float s = 0.0f;
    for (int o = lane; o < LS; o += 32)
        s += bf[o] * (__bfloat162float(sh_[o]) + __bfloat162float(sl_[o]));
    #pragma unroll
    for (int sft = 16; sft > 0; sft >>= 1)
        s += __shfl_xor_sync(0xFFFFFFFF, s, sft);
    if (lane == 0) g_cvec[w] = s;
}

__global__ void pack_out_split()
{
    long idx = (long)blockIdx.x * blockDim.x + threadIdx.x;
    const long total = (long)BB * NN_ * INNER_;
    if (idx >= total) return;
    long b = idx / ((long)NN_ * INNER_);
    long rem = idx - b * (long)NN_ * INNER_;
    long n = rem / INNER_, c = rem - n * INNER_;
    long h = c / DD, d = c - h * DD;
    wsplit(g_obh[((b * HH + h) * NN_ + n) * DD + d], g_outp_h, g_outp_l, idx);
}

// ---------------- launch ----------------
static inline dim3 eltGrid(long n) { return dim3((unsigned)((n + 255) / 256)); }
static inline unsigned cdiv(int a, int b) { return (unsigned)((a + b - 1) / b); }

#define GETP(T, v, sym) T* v; cudaGetSymbolAddress((void**)&v, sym)

extern "C" void kernel_launch(void* const* d_in, const int* in_sizes, int n_in,
                              void* d_out, int out_size)
{
    const float* inp  = (const float*)d_in[0];
    const float* x    = (const float*)d_in[1];
    const float* y    = (const float*)d_in[2];
    const float* Wq   = (const float*)d_in[3];
    const float* bq   = (const float*)d_in[4];
    const float* Wkv  = (const float*)d_in[5];
    const float* bkv  = (const float*)d_in[6];
    const float* Wf   = (const float*)d_in[7];
    const float* bf   = (const float*)d_in[8];
    const float* Wo   = (const float*)d_in[9];
    const float* bo   = (const float*)d_in[10];
    const float* m_k  = (const float*)d_in[11];
    // d_in[12] = m_v : unused (cross-attention v never feeds the output)
    const float* Sm_k = (const float*)d_in[13];
    const float* Sm_v = (const float*)d_in[14];
    float* out = (float*)d_out;

    GETP(bf16, p_inp_h, g_inp_h);   GETP(bf16, p_inp_l, g_inp_l);
    GETP(bf16, p_ctx_h, g_ctx_h);   GETP(bf16, p_ctx_l, g_ctx_l);
    GETP(bf16, p_Wq_h,  g_Wq_h);    GETP(bf16, p_Wq_l,  g_Wq_l);
    GETP(bf16, p_Wkv_h, g_Wkv_h);   GETP(bf16, p_Wkv_l, g_Wkv_l);
    GETP(bf16, p_Wo_h,  g_Wo_h);    GETP(bf16, p_Wo_l,  g_Wo_l);
    GETP(bf16, p_qlin_h,g_qlin_h);  GETP(bf16, p_qlin_l,g_qlin_l);
    GETP(bf16, p_kctx_h,g_kctx_h);  GETP(bf16, p_kctx_l,g_kctx_l);
    GETP(bf16, p_skv_h, g_skv_h);   GETP(bf16, p_skv_l, g_skv_l);
    GETP(bf16, p_Q_h,   g_Q_h);     GETP(bf16, p_Q_l,   g_Q_l);
    GETP(bf16, p_K_h,   g_K_h);     GETP(bf16, p_K_l,   g_K_l);
    GETP(bf16, p_Sk_h,  g_Sk_h);    GETP(bf16, p_Sk_l,  g_Sk_l);
    GETP(bf16, p_SvT_h, g_SvT_h);   GETP(bf16, p_SvT_l, g_SvT_l);
    GETP(bf16, p_WfT_h, g_WfT_h);   GETP(bf16, p_WfT_l, g_WfT_l);
    GETP(bf16, p_Ph,    g_Ph);      GETP(bf16, p_Pl,    g_Pl);
    GETP(bf16, p_S2h,   g_S2h);     GETP(bf16, p_S2l,   g_S2l);
    GETP(bf16, p_Gt_h,  g_Gt_h);    GETP(bf16, p_Gt_l,  g_Gt_l);
    GETP(bf16, p_outp_h,g_outp_h);  GETP(bf16, p_outp_l,g_outp_l);
    GETP(float, p_P,    g_P);
    GETP(float, p_S2,   g_S2);
    GETP(float, p_cvec, g_cvec);
    GETP(float, p_obh,  g_obh);

    // 0. split fp32 inputs
    split_arr<<<eltGrid((long)BB * NN_ * DIM_), 256>>>(inp, p_inp_h, p_inp_l, (long)BB * NN_ * DIM_);
    split_arr<<<eltGrid((long)INNER_ * DIM_), 256>>>(Wq, p_Wq_h, p_Wq_l, (long)INNER_ * DIM_);
    split_arr<<<eltGrid((long)2 * INNER_ * DIM_), 256>>>(Wkv, p_Wkv_h, p_Wkv_l, (long)2 * INNER_ * DIM_);
    split_arr<<<eltGrid((long)DIM_ * INNER_), 256>>>(Wo, p_Wo_h, p_Wo_l, (long)DIM_ * INNER_);
    pack_ctx_split<<<eltGrid((long)CTX * BB * DIM_), 256>>>(x, y);

    // 2. q_lin = inp @ Wq^T + bq   [8192, 512] K=512 -> split bf16
    gemm_bf<128,128><<<dim3(cdiv(INNER_,128), cdiv(BB*NN_,128), 1), 256>>>(
        p_inp_h, p_inp_l, DIM_, 0, p_Wq_h, p_Wq_l, DIM_, 0,
        bq, nullptr, 0, nullptr, 0, 0,
        nullptr, p_qlin_h, p_qlin_l, INNER_, 0, BB*NN_, INNER_, DIM_, 1.0f);

    // 3. k_ctx = context @ Wkv[0:512]^T + bkv[0:512]   [16384, 512] (v half dead)
    gemm_bf<128,128><<<dim3(cdiv(INNER_,128), cdiv(BB*CTX,128), 1), 256>>>(
        p_ctx_h, p_ctx_l, DIM_, 0, p_Wkv_h, p_Wkv_l, DIM_, 0,
        bkv, nullptr, 0, nullptr, 0, 0,
        nullptr, p_kctx_h, p_kctx_l, INNER_, 0, BB*CTX, INNER_, DIM_, 1.0f);

    // 4. skv = inp @ Wkv^T + bkv   [8192, 1024]
    gemm_bf<128,128><<<dim3(cdiv(2*INNER_,128), cdiv(BB*NN_,128), 1), 256>>>(
        p_inp_h, p_inp_l, DIM_, 0, p_Wkv_h, p_Wkv_l, DIM_, 0,
        bkv, nullptr, 0, nullptr, 0, 0,
        nullptr, p_skv_h, p_skv_l, 2*INNER_, 0, BB*NN_, 2*INNER_, DIM_, 1.0f);

    // 5. packs (+ memory tokens, + zero pads), WfT, cvec
    pack_Q_split  <<<eltGrid((long)ZZ * NN_ * DD), 256>>>();
    pack_K_split  <<<eltGrid((long)ZZ * LKP * DD), 256>>>(m_k);
    pack_Sk_split <<<eltGrid((long)ZZ * LSP * DD), 256>>>(Sm_k);
    pack_SvT_split<<<eltGrid((long)ZZ * DD * LSP), 256>>>(Sm_v);
    transpose_WfT <<<eltGrid((long)LKP * LSP), 256>>>(Wf);
    calc_cvec     <<<cdiv(ZZ * DD * 32, 256), 256>>>(bf);

    // 6. cross scores: P = SCALE * Q @ K^T  [64 x 1024 x 2051] K=64 -> fp32
    gemm_bf<128,128><<<dim3(cdiv(LK,128), cdiv(NN_,128), ZZ), 256>>>(
        p_Q_h, p_Q_l, DD, (long)NN_*DD, p_K_h, p_K_l, DD, (long)LKP*DD,
        nullptr, nullptr, 0, nullptr, 0, 0,
        p_P, nullptr, nullptr, LKP, (long)NN_*LKP, NN_, LK, DD, SCALE_);

    //    self scores: S2 = SCALE * Q @ Sk^T  [64 x 1024 x 1027]
    gemm_bf<128,128><<<dim3(cdiv(LS,128), cdiv(NN_,128), ZZ), 256>>>(
        p_Q_h, p_Q_l, DD, (long)NN_*DD, p_Sk_h, p_Sk_l, DD, (long)LSP*DD,
        nullptr, nullptr, 0, nullptr, 0, 0,
        p_S2, nullptr, nullptr, LSP, (long)NN_*LSP, NN_, LS, DD, SCALE_);

    // 7. softmax -> split bf16 (pads zeroed)
    softmax_split<<<ZZ * NN_, 256>>>(p_P, p_Ph, p_Pl, LK, LKP);
    softmax_split<<<ZZ * NN_, 256>>>(p_S2, p_S2h, p_S2l, LS, LSP);

    // 8a. Gt[z][d,k] = sum_o Sv[o,d] Wf[o,k]  [64 x (64 x 2064), K=1040] -> split
    //     (N = LKP so pad cols are WRITTEN as zeros; needed by 8c's K=2064)
    gemm_bf<64,128><<<dim3(cdiv(LKP,128), 1, ZZ), 256>>>(
        p_SvT_h, p_SvT_l, LSP, (long)DD*LSP, p_WfT_h, p_WfT_l, LSP, 0,
        nullptr, nullptr, 0, nullptr, 0, 0,
        nullptr, p_Gt_h, p_Gt_l, LKP, (long)DD*LKP, DD, LKP, LSP, 1.0f);

    // 8b. obh = S2 @ Sv   [64 x 1024 x 64, K=1040] -> fp32
    gemm_bf<128,64><<<dim3(1, cdiv(NN_,128), ZZ), 256>>>(
        p_S2h, p_S2l, LSP, (long)NN_*LSP, p_SvT_h, p_SvT_l, LSP, (long)DD*LSP,
        nullptr, nullptr, 0, nullptr, 0, 0,
        p_obh, nullptr, nullptr, DD, (long)NN_*DD, NN_, DD, LSP, 1.0f);

    // 8c. obh += P @ Gt^T + cvec   [64 x 1024 x 64, K=2064] (in-place)
    gemm_bf<128,64><<<dim3(1, cdiv(NN_,128), ZZ), 256>>>(
        p_Ph, p_Pl, LKP, (long)NN_*LKP, p_Gt_h, p_Gt_l, LKP, (long)DD*LKP,
        nullptr, p_cvec, DD, p_obh, DD, (long)NN_*DD,
        p_obh, nullptr, nullptr, DD, (long)NN_*DD, NN_, DD, LKP, 1.0f);

    // 9. merge heads -> split bf16
    pack_out_split<<<eltGrid((long)BB * NN_ * INNER_), 256>>>();

    // 10. final = out @ Wo^T + bo   [8192, 512] K=512 -> fp32 d_out
    gemm_bf<128,128><<<dim3(cdiv(DIM_,128), cdiv(BB*NN_,128), 1), 256>>>(
        p_outp_h, p_outp_l, INNER_, 0, p_Wo_h, p_Wo_l, INNER_, 0,
        bo, nullptr, 0, nullptr, 0, 0,
        out, nullptr, nullptr, DIM_, 0, BB*NN_, DIM_, INNER_, 1.0f);
}